// round 2
// baseline (speedup 1.0000x reference)
#include <cuda_runtime.h>

// Problem constants
#define Bn   4
#define Cn   256
#define Hn   128
#define Wn   256
#define CQKn 64
#define COUTn 256
#define HWn  (Hn * Wn)   // 32768

// Scratch for q, k, v projections (device globals: allowed scratch path)
__device__ float g_q[(size_t)Bn * CQKn  * HWn];  // 33.5 MB
__device__ float g_k[(size_t)Bn * CQKn  * HWn];  // 33.5 MB
__device__ float g_v[(size_t)Bn * COUTn * HWn];  // 134 MB

// ---------------------------------------------------------------------------
// Projection GEMM: Y[b, m, p] = sum_c Wm[m, c] * X[b, c, p] + bias[m]
// Block tile: M=64, N=128, K-chunk=32. Threads: 256 (16x16), micro 4(m)x8(n).
// ---------------------------------------------------------------------------
__global__ __launch_bounds__(256) void proj_kernel(
    const float* __restrict__ X, const float* __restrict__ Wm,
    const float* __restrict__ bias, float* __restrict__ Y, int M)
{
    __shared__ float Ws[64 * 33];    // [m][kk], pad 33
    __shared__ float Xs[32 * 132];   // [kk][n], pad 132 (16B aligned rows)

    const int tid = threadIdx.x;
    const int tx = tid & 15;         // n group
    const int ty = tid >> 4;         // m group
    const int n0 = blockIdx.x * 128;
    const int bm = blockIdx.y * 64;
    const int b  = blockIdx.z;

    const float* Xb = X + (size_t)b * Cn * HWn;

    float acc[4][8];
#pragma unroll
    for (int i = 0; i < 4; i++)
#pragma unroll
        for (int j = 0; j < 8; j++) acc[i][j] = 0.f;

    for (int k0 = 0; k0 < Cn; k0 += 32) {
        // Load W tile 64x32 (coalesced 128B rows)
#pragma unroll
        for (int idx = tid; idx < 64 * 32; idx += 256) {
            int m  = idx >> 5;
            int kk = idx & 31;
            Ws[m * 33 + kk] = Wm[(size_t)(bm + m) * Cn + k0 + kk];
        }
        // Load X tile 32x128 (coalesced)
#pragma unroll
        for (int idx = tid; idx < 32 * 128; idx += 256) {
            int kk = idx >> 7;
            int n  = idx & 127;
            Xs[kk * 132 + n] = Xb[(size_t)(k0 + kk) * HWn + n0 + n];
        }
        __syncthreads();

#pragma unroll
        for (int kk = 0; kk < 32; kk++) {
            float a0 = Ws[(ty * 4 + 0) * 33 + kk];
            float a1 = Ws[(ty * 4 + 1) * 33 + kk];
            float a2 = Ws[(ty * 4 + 2) * 33 + kk];
            float a3 = Ws[(ty * 4 + 3) * 33 + kk];
            float4 x0 = *(const float4*)&Xs[kk * 132 + tx * 8];
            float4 x1 = *(const float4*)&Xs[kk * 132 + tx * 8 + 4];
            float xb[8] = {x0.x, x0.y, x0.z, x0.w, x1.x, x1.y, x1.z, x1.w};
#pragma unroll
            for (int j = 0; j < 8; j++) {
                acc[0][j] += a0 * xb[j];
                acc[1][j] += a1 * xb[j];
                acc[2][j] += a2 * xb[j];
                acc[3][j] += a3 * xb[j];
            }
        }
        __syncthreads();
    }

    // Epilogue: add bias, store float4 x2 per m-row
#pragma unroll
    for (int um = 0; um < 4; um++) {
        int m = bm + ty * 4 + um;
        float bb = bias[m];
        size_t base = (size_t)b * M * HWn + (size_t)m * HWn + n0 + tx * 8;
        float4 o0 = {acc[um][0] + bb, acc[um][1] + bb, acc[um][2] + bb, acc[um][3] + bb};
        float4 o1 = {acc[um][4] + bb, acc[um][5] + bb, acc[um][6] + bb, acc[um][7] + bb};
        *(float4*)&Y[base]     = o0;
        *(float4*)&Y[base + 4] = o1;
    }
}

// ---------------------------------------------------------------------------
// Width-axial attention. One block per (query-tile qt, h, b).
//   energy[i, j] = sum_d q[d, wq0+i] * k[d, j]      (i<64 queries, j<256 keys)
//   att = softmax_j(energy)  (normalization deferred to epilogue)
//   out[o, wq0+i] = (sum_j v[o, j] * exp(e[i,j]-max_i)) * (1/sum_i)
// Shared layout (floats):
//   q_s  [d][i]     64*64    @ 0
//   k_s  [d][j]     64*256   @ 4096
//   a_s  [j][i]     256*68   @ 20480   (transposed energy/att, pad 68)
//   v_s  [o][jj]    256*33   @ 37888   (32-key chunk of v, pad 33)
//   red             576      @ 46336   (max[256] | sum[256] | rinv[64])
// Total 46912 floats = 187648 B dynamic smem.
// ---------------------------------------------------------------------------
__global__ __launch_bounds__(256) void attn_kernel(float* __restrict__ out)
{
    extern __shared__ float sm[];
    float* q_s = sm;
    float* k_s = sm + 4096;
    float* a_s = sm + 20480;
    float* v_s = sm + 37888;
    float* red = sm + 46336;

    const int tid = threadIdx.x;
    const int tx = tid & 15;
    const int ty = tid >> 4;
    const int qt = blockIdx.x;     // query tile (0..3)
    const int h  = blockIdx.y;
    const int b  = blockIdx.z;
    const int wq0 = qt * 64;

    const size_t rowqk = (size_t)b * CQKn * HWn + (size_t)h * Wn;

    // Load q tile [64 d][64 i]
#pragma unroll
    for (int idx = tid; idx < 64 * 64; idx += 256) {
        int d = idx >> 6, i = idx & 63;
        q_s[idx] = g_q[rowqk + (size_t)d * HWn + wq0 + i];
    }
    // Load k slice [64 d][256 j]
#pragma unroll
    for (int idx = tid; idx < 64 * 256; idx += 256) {
        int d = idx >> 8, j = idx & 255;
        k_s[idx] = g_k[rowqk + (size_t)d * HWn + j];
    }
    __syncthreads();

    // --- Energy GEMM: e[m][u] = att[j = ty+16m][i = tx*4+u] ---
    float e[16][4];
#pragma unroll
    for (int m = 0; m < 16; m++)
#pragma unroll
        for (int u = 0; u < 4; u++) e[m][u] = 0.f;

    for (int d = 0; d < 64; d++) {
        float4 qa = *(const float4*)&q_s[d * 64 + tx * 4];
#pragma unroll
        for (int m = 0; m < 16; m++) {
            float kb = k_s[d * 256 + ty + 16 * m];
            e[m][0] += kb * qa.x;
            e[m][1] += kb * qa.y;
            e[m][2] += kb * qa.z;
            e[m][3] += kb * qa.w;
        }
    }
#pragma unroll
    for (int m = 0; m < 16; m++) {
        float4 st = {e[m][0], e[m][1], e[m][2], e[m][3]};
        *(float4*)&a_s[(ty + 16 * m) * 68 + tx * 4] = st;
    }
    __syncthreads();

    // --- Softmax over j per query i (4 threads per i) ---
    {
        const int i  = tid & 63;
        const int qr = tid >> 6;           // j quarter
        float lm = -1e30f;
#pragma unroll 8
        for (int jj = 0; jj < 64; jj++)
            lm = fmaxf(lm, a_s[(qr * 64 + jj) * 68 + i]);
        red[qr * 64 + i] = lm;
        __syncthreads();
        float rm = fmaxf(fmaxf(red[i], red[64 + i]), fmaxf(red[128 + i], red[192 + i]));
        float ls = 0.f;
#pragma unroll 8
        for (int jj = 0; jj < 64; jj++) {
            float ex = __expf(a_s[(qr * 64 + jj) * 68 + i] - rm);
            a_s[(qr * 64 + jj) * 68 + i] = ex;
            ls += ex;
        }
        red[256 + qr * 64 + i] = ls;
        __syncthreads();
        if (tid < 64) {
            float s = red[256 + tid] + red[320 + tid] + red[384 + tid] + red[448 + tid];
            red[512 + tid] = 1.0f / s;
        }
        // visibility of red[512..] + a_s covered by first sync in AV loop
    }

    // --- AV GEMM: out[o = ty+16r][i = tx*4+u], stream v in 32-key chunks ---
    float acc2[16][4];
#pragma unroll
    for (int r = 0; r < 16; r++)
#pragma unroll
        for (int u = 0; u < 4; u++) acc2[r][u] = 0.f;

    const size_t vbase = (size_t)b * COUTn * HWn + (size_t)h * Wn;

    for (int jc = 0; jc < 8; jc++) {
        const int jbase = jc * 32;
        __syncthreads();   // protect v_s reuse (and rinv/a_s on first iter)
#pragma unroll
        for (int idx = tid; idx < 256 * 32; idx += 256) {
            int o = idx >> 5, jj = idx & 31;
            v_s[o * 33 + jj] = g_v[vbase + (size_t)o * HWn + jbase + jj];
        }
        __syncthreads();

#pragma unroll 4
        for (int jj = 0; jj < 32; jj++) {
            float4 aa = *(const float4*)&a_s[(jbase + jj) * 68 + tx * 4];
#pragma unroll
            for (int r = 0; r < 16; r++) {
                float vv = v_s[(ty + 16 * r) * 33 + jj];
                acc2[r][0] += vv * aa.x;
                acc2[r][1] += vv * aa.y;
                acc2[r][2] += vv * aa.z;
                acc2[r][3] += vv * aa.w;
            }
        }
    }

    // Epilogue: apply deferred 1/sum, store float4 (fully coalesced)
    float rv0 = red[512 + tx * 4 + 0];
    float rv1 = red[512 + tx * 4 + 1];
    float rv2 = red[512 + tx * 4 + 2];
    float rv3 = red[512 + tx * 4 + 3];
    size_t obase = (size_t)b * COUTn * HWn + (size_t)h * Wn + wq0 + tx * 4;
#pragma unroll
    for (int r = 0; r < 16; r++) {
        int o = ty + 16 * r;
        float4 ov = {acc2[r][0] * rv0, acc2[r][1] * rv1, acc2[r][2] * rv2, acc2[r][3] * rv3};
        *(float4*)&out[obase + (size_t)o * HWn] = ov;
    }
}

// ---------------------------------------------------------------------------
extern "C" void kernel_launch(void* const* d_in, const int* in_sizes, int n_in,
                              void* d_out, int out_size)
{
    const float* flow   = (const float*)d_in[0];
    const float* de_out = (const float*)d_in[1];
    const float* Wq     = (const float*)d_in[2];
    const float* bq     = (const float*)d_in[3];
    const float* Wk     = (const float*)d_in[4];
    const float* bk     = (const float*)d_in[5];
    const float* Wv     = (const float*)d_in[6];
    const float* bv     = (const float*)d_in[7];
    float* out = (float*)d_out;

    float *qp, *kp, *vp;
    cudaGetSymbolAddress((void**)&qp, g_q);
    cudaGetSymbolAddress((void**)&kp, g_k);
    cudaGetSymbolAddress((void**)&vp, g_v);

    const int ATT_SMEM = 46912 * 4;  // 187648 B
    cudaFuncSetAttribute(attn_kernel, cudaFuncAttributeMaxDynamicSharedMemorySize, ATT_SMEM);

    dim3 blk(256);
    // q = Wq * de_out + bq
    proj_kernel<<<dim3(HWn / 128, CQKn / 64, Bn), blk>>>(de_out, Wq, bq, qp, CQKn);
    // k = Wk * flow + bk
    proj_kernel<<<dim3(HWn / 128, CQKn / 64, Bn), blk>>>(flow, Wk, bk, kp, CQKn);
    // v = Wv * flow + bv
    proj_kernel<<<dim3(HWn / 128, COUTn / 64, Bn), blk>>>(flow, Wv, bv, vp, COUTn);
    // attention
    attn_kernel<<<dim3(Wn / 64, Hn, Bn), blk, ATT_SMEM>>>(out);
}

// round 6
// speedup vs baseline: 1.8050x; 1.8050x over previous
#include <cuda_runtime.h>
#include <cuda_fp16.h>
#include <cstdint>

#define Bn 4
#define Cn 256
#define Hn 128
#define Wn 256
#define HWn 32768
#define PS 72   // smem row stride in halves (144B: conflict-free for frag loads)

// q,k: [b][p][64] pixel-major; v: [b][o][p]
__device__ float g_q[(size_t)Bn * HWn * 64];
__device__ float g_k[(size_t)Bn * HWn * 64];
__device__ float g_v[(size_t)Bn * 256 * HWn];

// ---------------- helpers ----------------
static __device__ __forceinline__ void split2(float x, __half& h, __half& l) {
    h = __float2half_rn(x);
    l = __float2half_rn(x - __half2float(h));
}
static __device__ __forceinline__ uint32_t pack2(__half a, __half b) {
    __half2 t = __halves2half2(a, b);
    return *(uint32_t*)&t;
}
static __device__ __forceinline__ void mma16816(float* d, const uint32_t* a, const uint32_t* b) {
    asm volatile("mma.sync.aligned.m16n8k16.row.col.f32.f16.f16.f32 "
        "{%0,%1,%2,%3}, {%4,%5,%6,%7}, {%8,%9}, {%0,%1,%2,%3};"
        : "+f"(d[0]), "+f"(d[1]), "+f"(d[2]), "+f"(d[3])
        : "r"(a[0]), "r"(a[1]), "r"(a[2]), "r"(a[3]), "r"(b[0]), "r"(b[1]));
}
// A frag (m16 x k16) from row-major smem [m][k], stride PS
static __device__ __forceinline__ void ldA(uint32_t* a, const __half* t, int m0, int k0, int g, int c) {
    a[0] = *(const uint32_t*)(t + (m0 + g) * PS + k0 + 2 * c);
    a[1] = *(const uint32_t*)(t + (m0 + g + 8) * PS + k0 + 2 * c);
    a[2] = *(const uint32_t*)(t + (m0 + g) * PS + k0 + 2 * c + 8);
    a[3] = *(const uint32_t*)(t + (m0 + g + 8) * PS + k0 + 2 * c + 8);
}
// B frag (k16 x n8) from row-major smem [n][k], stride PS
static __device__ __forceinline__ void ldB(uint32_t* b, const __half* t, int n0, int k0, int g, int c) {
    b[0] = *(const uint32_t*)(t + (n0 + g) * PS + k0 + 2 * c);
    b[1] = *(const uint32_t*)(t + (n0 + g) * PS + k0 + 2 * c + 8);
}

// ---------------------------------------------------------------------------
// q/k projection: D[128 p, 64 d] = X^T[p,c] * W[d,c]^T + bias   (3-mma split)
// grid (HWn/128, 2, B), 256 threads, warps 4(m) x 2(n)
// ---------------------------------------------------------------------------
#define QK_SMEM ((128*2 + 64*2) * PS * 2)
__global__ __launch_bounds__(256) void qk_proj(
    const float* __restrict__ de_out, const float* __restrict__ flow,
    const float* __restrict__ Wq, const float* __restrict__ bq,
    const float* __restrict__ Wk, const float* __restrict__ bk)
{
    extern __shared__ __half smh[];
    __half* xh = smh;
    __half* xl = xh + 128 * PS;
    __half* wh = xl + 128 * PS;
    __half* wl = wh + 64 * PS;

    const int tid = threadIdx.x, w = tid >> 5, lane = tid & 31;
    const int g = lane >> 2, c = lane & 3;
    const int wm = w & 3, wn = w >> 2;
    const int p0 = blockIdx.x * 128, isK = blockIdx.y, b = blockIdx.z;

    const float* X    = isK ? flow : de_out;
    const float* Wm   = isK ? Wk : Wq;
    const float* bias = isK ? bk : bq;
    float*       Y    = isK ? g_k : g_q;
    const float* Xb = X + (size_t)b * Cn * HWn;

    float acc[2][4][4] = {};

    for (int kc = 0; kc < 4; kc++) {
        // X chunk [128 p][64 c] (transposing load)
        for (int i = tid; i < 8192; i += 256) {
            int cc = i >> 7, p = i & 127;
            __half h, l;
            split2(Xb[(size_t)(kc * 64 + cc) * HWn + p0 + p], h, l);
            xh[p * PS + cc] = h;
            xl[p * PS + cc] = l;
        }
        // W chunk [64 d][64 c]
        for (int i = tid * 2; i < 4096; i += 512) {
            int d = i >> 6, cc = i & 63;
            __half h0, l0, h1, l1;
            split2(Wm[d * 256 + kc * 64 + cc], h0, l0);
            split2(Wm[d * 256 + kc * 64 + cc + 1], h1, l1);
            *(uint32_t*)&wh[d * PS + cc] = pack2(h0, h1);
            *(uint32_t*)&wl[d * PS + cc] = pack2(l0, l1);
        }
        __syncthreads();
#pragma unroll
        for (int kt = 0; kt < 4; kt++) {
            uint32_t ah0[4], al0[4], ah1[4], al1[4];
            ldA(ah0, xh, wm * 32, kt * 16, g, c);
            ldA(al0, xl, wm * 32, kt * 16, g, c);
            ldA(ah1, xh, wm * 32 + 16, kt * 16, g, c);
            ldA(al1, xl, wm * 32 + 16, kt * 16, g, c);
#pragma unroll
            for (int nt = 0; nt < 4; nt++) {
                uint32_t bh[2], bl[2];
                ldB(bh, wh, wn * 32 + nt * 8, kt * 16, g, c);
                ldB(bl, wl, wn * 32 + nt * 8, kt * 16, g, c);
                mma16816(acc[0][nt], ah0, bh);
                mma16816(acc[0][nt], ah0, bl);
                mma16816(acc[0][nt], al0, bh);
                mma16816(acc[1][nt], ah1, bh);
                mma16816(acc[1][nt], ah1, bl);
                mma16816(acc[1][nt], al1, bh);
            }
        }
        __syncthreads();
    }
#pragma unroll
    for (int mt = 0; mt < 2; mt++) {
#pragma unroll
        for (int nt = 0; nt < 4; nt++) {
            int dcol = wn * 32 + nt * 8 + 2 * c;
            float b0 = bias[dcol], b1 = bias[dcol + 1];
            size_t base = ((size_t)b * HWn + p0 + wm * 32 + mt * 16 + g) * 64 + dcol;
            float2 v0 = {acc[mt][nt][0] + b0, acc[mt][nt][1] + b1};
            float2 v1 = {acc[mt][nt][2] + b0, acc[mt][nt][3] + b1};
            *(float2*)&Y[base] = v0;
            *(float2*)&Y[base + 8 * 64] = v1;
        }
    }
}

// ---------------------------------------------------------------------------
// v projection: D[128 p, 128 o] = X^T[p,c] * Wv[o,c]^T + bias   (3-mma split)
// grid (HWn/128, 2, B), 256 threads, warps 4(m) x 2(n); out g_v[b][o][p]
// ---------------------------------------------------------------------------
#define V_SMEM ((128*2 + 128*2) * PS * 2)
__global__ __launch_bounds__(256) void v_proj(
    const float* __restrict__ flow, const float* __restrict__ Wv,
    const float* __restrict__ bv)
{
    extern __shared__ __half smh[];
    __half* xh = smh;
    __half* xl = xh + 128 * PS;
    __half* wh = xl + 128 * PS;
    __half* wl = wh + 128 * PS;

    const int tid = threadIdx.x, w = tid >> 5, lane = tid & 31;
    const int g = lane >> 2, c = lane & 3;
    const int wm = w & 3, wn = w >> 2;
    const int p0 = blockIdx.x * 128, ot = blockIdx.y, b = blockIdx.z;
    const float* Xb = flow + (size_t)b * Cn * HWn;

    float acc[2][8][4] = {};

    for (int kc = 0; kc < 4; kc++) {
        for (int i = tid; i < 8192; i += 256) {
            int cc = i >> 7, p = i & 127;
            __half h, l;
            split2(Xb[(size_t)(kc * 64 + cc) * HWn + p0 + p], h, l);
            xh[p * PS + cc] = h;
            xl[p * PS + cc] = l;
        }
        for (int i = tid * 2; i < 8192; i += 512) {
            int o = i >> 6, cc = i & 63;
            __half h0, l0, h1, l1;
            split2(Wv[(ot * 128 + o) * 256 + kc * 64 + cc], h0, l0);
            split2(Wv[(ot * 128 + o) * 256 + kc * 64 + cc + 1], h1, l1);
            *(uint32_t*)&wh[o * PS + cc] = pack2(h0, h1);
            *(uint32_t*)&wl[o * PS + cc] = pack2(l0, l1);
        }
        __syncthreads();
#pragma unroll
        for (int kt = 0; kt < 4; kt++) {
            uint32_t ah0[4], al0[4], ah1[4], al1[4];
            ldA(ah0, xh, wm * 32, kt * 16, g, c);
            ldA(al0, xl, wm * 32, kt * 16, g, c);
            ldA(ah1, xh, wm * 32 + 16, kt * 16, g, c);
            ldA(al1, xl, wm * 32 + 16, kt * 16, g, c);
#pragma unroll
            for (int nt = 0; nt < 8; nt++) {
                uint32_t bh[2], bl[2];
                ldB(bh, wh, wn * 64 + nt * 8, kt * 16, g, c);
                ldB(bl, wl, wn * 64 + nt * 8, kt * 16, g, c);
                mma16816(acc[0][nt], ah0, bh);
                mma16816(acc[0][nt], ah0, bl);
                mma16816(acc[0][nt], al0, bh);
                mma16816(acc[1][nt], ah1, bh);
                mma16816(acc[1][nt], ah1, bl);
                mma16816(acc[1][nt], al1, bh);
            }
        }
        __syncthreads();
    }
#pragma unroll
    for (int mt = 0; mt < 2; mt++) {
#pragma unroll
        for (int nt = 0; nt < 8; nt++) {
            int o = ot * 128 + wn * 64 + nt * 8 + 2 * c;
            int p = p0 + wm * 32 + mt * 16 + g;
            float b0 = bv[o], b1 = bv[o + 1];
            g_v[(size_t)(b * 256 + o) * HWn + p]           = acc[mt][nt][0] + b0;
            g_v[(size_t)(b * 256 + o + 1) * HWn + p]       = acc[mt][nt][1] + b1;
            g_v[(size_t)(b * 256 + o) * HWn + p + 8]       = acc[mt][nt][2] + b0;
            g_v[(size_t)(b * 256 + o + 1) * HWn + p + 8]   = acc[mt][nt][3] + b1;
        }
    }
}

// ---------------------------------------------------------------------------
// Fused attention per (qt, h, b): warp owns 16 q rows x 256 keys.
// E (3-mma split) -> warp-local softmax -> fragment-chained AV (3-mma split).
// grid (2, 128, B), 256 threads (8 warps).
// ---------------------------------------------------------------------------
#define A_SMEM ((128*2 + 256*2 + 64*2) * PS * 2)
__global__ __launch_bounds__(256) void attn(float* __restrict__ out)
{
    extern __shared__ __half smh[];
    __half* qh = smh;
    __half* ql = qh + 128 * PS;
    __half* kh = ql + 128 * PS;
    __half* kl = kh + 256 * PS;
    __half* vh = kl + 256 * PS;
    __half* vl = vh + 64 * PS;

    const int tid = threadIdx.x, w = tid >> 5, lane = tid & 31;
    const int g = lane >> 2, c = lane & 3;
    const int qt = blockIdx.x, h = blockIdx.y, b = blockIdx.z;
    const int w0 = qt * 128;

    const float* qg = g_q + ((size_t)b * HWn + h * Wn + w0) * 64;
    const float* kg = g_k + ((size_t)b * HWn + h * Wn) * 64;
    for (int i = tid * 2; i < 8192; i += 512) {
        int r = i >> 6, d = i & 63;
        __half h0, l0, h1, l1;
        split2(qg[r * 64 + d], h0, l0);
        split2(qg[r * 64 + d + 1], h1, l1);
        *(uint32_t*)&qh[r * PS + d] = pack2(h0, h1);
        *(uint32_t*)&ql[r * PS + d] = pack2(l0, l1);
    }
    for (int i = tid * 2; i < 16384; i += 512) {
        int r = i >> 6, d = i & 63;
        __half h0, l0, h1, l1;
        split2(kg[r * 64 + d], h0, l0);
        split2(kg[r * 64 + d + 1], h1, l1);
        *(uint32_t*)&kh[r * PS + d] = pack2(h0, h1);
        *(uint32_t*)&kl[r * PS + d] = pack2(l0, l1);
    }
    __syncthreads();

    // --- E = q k^T : warp rows m0 = w*16, all 256 keys ---
    float e[32][4] = {};
#pragma unroll
    for (int kt = 0; kt < 4; kt++) {
        uint32_t ah[4], al[4];
        ldA(ah, qh, w * 16, kt * 16, g, c);
        ldA(al, ql, w * 16, kt * 16, g, c);
#pragma unroll
        for (int nt = 0; nt < 32; nt++) {
            uint32_t bh[2], bl[2];
            ldB(bh, kh, nt * 8, kt * 16, g, c);
            ldB(bl, kl, nt * 8, kt * 16, g, c);
            mma16816(e[nt], ah, bh);
            mma16816(e[nt], ah, bl);
            mma16816(e[nt], al, bh);
        }
    }

    // --- warp-local softmax (lane owns rows g and g+8; cols spread over c) ---
    float m0 = -1e30f, m1 = -1e30f;
#pragma unroll
    for (int nt = 0; nt < 32; nt++) {
        m0 = fmaxf(m0, fmaxf(e[nt][0], e[nt][1]));
        m1 = fmaxf(m1, fmaxf(e[nt][2], e[nt][3]));
    }
    m0 = fmaxf(m0, __shfl_xor_sync(0xffffffffu, m0, 1));
    m0 = fmaxf(m0, __shfl_xor_sync(0xffffffffu, m0, 2));
    m1 = fmaxf(m1, __shfl_xor_sync(0xffffffffu, m1, 1));
    m1 = fmaxf(m1, __shfl_xor_sync(0xffffffffu, m1, 2));

    float s0 = 0.f, s1 = 0.f;
    uint32_t ah_[64], al_[64];
#pragma unroll
    for (int nt = 0; nt < 32; nt++) {
        float p00 = __expf(e[nt][0] - m0), p01 = __expf(e[nt][1] - m0);
        float p10 = __expf(e[nt][2] - m1), p11 = __expf(e[nt][3] - m1);
        s0 += p00 + p01;
        s1 += p10 + p11;
        __half h0, l0, h1, l1;
        split2(p00, h0, l0); split2(p01, h1, l1);
        ah_[2 * nt] = pack2(h0, h1); al_[2 * nt] = pack2(l0, l1);
        split2(p10, h0, l0); split2(p11, h1, l1);
        ah_[2 * nt + 1] = pack2(h0, h1); al_[2 * nt + 1] = pack2(l0, l1);
    }
    s0 += __shfl_xor_sync(0xffffffffu, s0, 1);
    s0 += __shfl_xor_sync(0xffffffffu, s0, 2);
    s1 += __shfl_xor_sync(0xffffffffu, s1, 1);
    s1 += __shfl_xor_sync(0xffffffffu, s1, 2);
    const float rinv0 = 1.0f / s0, rinv1 = 1.0f / s1;

    // --- AV: out rows = same 16 q rows; loop o in 4 chunks of 64 ---
    const size_t vbase = (size_t)b * 256 * HWn + h * Wn;
    for (int ot = 0; ot < 4; ot++) {
        float oacc[8][4] = {};
#pragma unroll
        for (int jc = 0; jc < 4; jc++) {
            __syncthreads();
            for (int i = tid * 2; i < 4096; i += 512) {
                int o = i >> 6, j = i & 63;
                __half h0, l0, h1, l1;
                split2(g_v[vbase + (size_t)(ot * 64 + o) * HWn + jc * 64 + j], h0, l0);
                split2(g_v[vbase + (size_t)(ot * 64 + o) * HWn + jc * 64 + j + 1], h1, l1);
                *(uint32_t*)&vh[o * PS + j] = pack2(h0, h1);
                *(uint32_t*)&vl[o * PS + j] = pack2(l0, l1);
            }
            __syncthreads();
#pragma unroll
            for (int kt = 0; kt < 4; kt++) {
                const uint32_t* Ah = &ah_[4 * (jc * 4 + kt)];
                const uint32_t* Al = &al_[4 * (jc * 4 + kt)];
#pragma unroll
                for (int nt = 0; nt < 8; nt++) {
                    uint32_t bh[2], bl[2];
                    ldB(bh, vh, nt * 8, kt * 16, g, c);
                    ldB(bl, vl, nt * 8, kt * 16, g, c);
                    mma16816(oacc[nt], Ah, bh);
                    mma16816(oacc[nt], Ah, bl);
                    mma16816(oacc[nt], Al, bh);
                }
            }
        }
        // store this o-chunk: out[b][o][h][w0 + q]
#pragma unroll
        for (int nt = 0; nt < 8; nt++) {
            int o = ot * 64 + nt * 8 + 2 * c;
            size_t i0 = ((size_t)(b * 256 + o) * Hn + h) * Wn + w0 + w * 16 + g;
            out[i0]           = oacc[nt][0] * rinv0;
            out[i0 + HWn]     = oacc[nt][1] * rinv0;
            out[i0 + 8]       = oacc[nt][2] * rinv1;
            out[i0 + HWn + 8] = oacc[nt][3] * rinv1;
        }
    }
}

// ---------------------------------------------------------------------------
extern "C" void kernel_launch(void* const* d_in, const int* in_sizes, int n_in,
                              void* d_out, int out_size)
{
    const float* flow   = (const float*)d_in[0];
    const float* de_out = (const float*)d_in[1];
    const float* Wq     = (const float*)d_in[2];
    const float* bq     = (const float*)d_in[3];
    const float* Wk     = (const float*)d_in[4];
    const float* bk     = (const float*)d_in[5];
    const float* Wv     = (const float*)d_in[6];
    const float* bv     = (const float*)d_in[7];
    float* out = (float*)d_out;

    cudaFuncSetAttribute(qk_proj, cudaFuncAttributeMaxDynamicSharedMemorySize, QK_SMEM);
    cudaFuncSetAttribute(v_proj,  cudaFuncAttributeMaxDynamicSharedMemorySize, V_SMEM);
    cudaFuncSetAttribute(attn,    cudaFuncAttributeMaxDynamicSharedMemorySize, A_SMEM);

    qk_proj<<<dim3(HWn / 128, 2, Bn), 256, QK_SMEM>>>(de_out, flow, Wq, bq, Wk, bk);
    v_proj<<<dim3(HWn / 128, 2, Bn), 256, V_SMEM>>>(flow, Wv, bv);
    attn<<<dim3(Wn / 128, Hn, Bn), 256, A_SMEM>>>(out);
}

// round 7
// speedup vs baseline: 2.6244x; 1.4539x over previous
#include <cuda_runtime.h>
#include <cuda_fp16.h>
#include <cstdint>

#define Bn 4
#define Cn 256
#define Hn 128
#define Wn 256
#define HWn 32768
#define PS 72    // smem stride (halves) for 64-wide K-chunk tiles
#define PSV 264  // smem stride (halves) for v slab [256 o][256 j]

// q,k pre-split hi/lo fp16 [b][p][64]; v plain fp16 [b][o][p]
__device__ __half g_qh[(size_t)Bn * HWn * 64];
__device__ __half g_ql[(size_t)Bn * HWn * 64];
__device__ __half g_kh[(size_t)Bn * HWn * 64];
__device__ __half g_kl[(size_t)Bn * HWn * 64];
__device__ __half g_v [(size_t)Bn * 256 * HWn];

// ---------------- helpers ----------------
static __device__ __forceinline__ void split2(float x, __half& h, __half& l) {
    h = __float2half_rn(x);
    l = __float2half_rn(x - __half2float(h));
}
static __device__ __forceinline__ uint32_t pack2(__half a, __half b) {
    __half2 t = __halves2half2(a, b);
    return *(uint32_t*)&t;
}
static __device__ __forceinline__ void mma16816(float* d, const uint32_t* a, const uint32_t* b) {
    asm volatile("mma.sync.aligned.m16n8k16.row.col.f32.f16.f16.f32 "
        "{%0,%1,%2,%3}, {%4,%5,%6,%7}, {%8,%9}, {%0,%1,%2,%3};"
        : "+f"(d[0]), "+f"(d[1]), "+f"(d[2]), "+f"(d[3])
        : "r"(a[0]), "r"(a[1]), "r"(a[2]), "r"(a[3]), "r"(b[0]), "r"(b[1]));
}
// A frag (m16 x k16) from row-major smem [m][k]
static __device__ __forceinline__ void ldA(uint32_t* a, const __half* t, int m0, int k0,
                                           int g, int c, int stride) {
    a[0] = *(const uint32_t*)(t + (m0 + g) * stride + k0 + 2 * c);
    a[1] = *(const uint32_t*)(t + (m0 + g + 8) * stride + k0 + 2 * c);
    a[2] = *(const uint32_t*)(t + (m0 + g) * stride + k0 + 2 * c + 8);
    a[3] = *(const uint32_t*)(t + (m0 + g + 8) * stride + k0 + 2 * c + 8);
}
// B frag (k16 x n8) from row-major smem [n][k]
static __device__ __forceinline__ void ldB(uint32_t* b, const __half* t, int n0, int k0,
                                           int g, int c, int stride) {
    b[0] = *(const uint32_t*)(t + (n0 + g) * stride + k0 + 2 * c);
    b[1] = *(const uint32_t*)(t + (n0 + g) * stride + k0 + 2 * c + 8);
}

// ---------------------------------------------------------------------------
// q/k projection (3-term split): D[128 p, 64 d] = X^T * W^T + bias
// grid (HWn/128, 2, B), 256 threads, warps 4(m) x 2(n). Out: hi/lo half pairs.
// ---------------------------------------------------------------------------
#define QK_SMEM ((128*2 + 64*2) * PS * 2)
__global__ __launch_bounds__(256) void qk_proj(
    const float* __restrict__ de_out, const float* __restrict__ flow,
    const float* __restrict__ Wq, const float* __restrict__ bq,
    const float* __restrict__ Wk, const float* __restrict__ bk)
{
    extern __shared__ __half smh[];
    __half* xh = smh;
    __half* xl = xh + 128 * PS;
    __half* wh = xl + 128 * PS;
    __half* wl = wh + 64 * PS;

    const int tid = threadIdx.x, w = tid >> 5, lane = tid & 31;
    const int g = lane >> 2, c = lane & 3;
    const int wm = w & 3, wn = w >> 2;
    const int p0 = blockIdx.x * 128, isK = blockIdx.y, b = blockIdx.z;

    const float* X    = isK ? flow : de_out;
    const float* Wm   = isK ? Wk : Wq;
    const float* bias = isK ? bk : bq;
    __half*      Yh   = isK ? g_kh : g_qh;
    __half*      Yl   = isK ? g_kl : g_ql;
    const float* Xb = X + (size_t)b * Cn * HWn;

    float acc[2][4][4] = {};

    for (int kc = 0; kc < 4; kc++) {
        for (int i = tid; i < 8192; i += 256) {
            int cc = i >> 7, p = i & 127;
            __half h, l;
            split2(Xb[(size_t)(kc * 64 + cc) * HWn + p0 + p], h, l);
            xh[p * PS + cc] = h;
            xl[p * PS + cc] = l;
        }
        for (int i = tid * 2; i < 4096; i += 512) {
            int d = i >> 6, cc = i & 63;
            __half h0, l0, h1, l1;
            split2(Wm[d * 256 + kc * 64 + cc], h0, l0);
            split2(Wm[d * 256 + kc * 64 + cc + 1], h1, l1);
            *(uint32_t*)&wh[d * PS + cc] = pack2(h0, h1);
            *(uint32_t*)&wl[d * PS + cc] = pack2(l0, l1);
        }
        __syncthreads();
#pragma unroll
        for (int kt = 0; kt < 4; kt++) {
            uint32_t ah0[4], al0[4], ah1[4], al1[4];
            ldA(ah0, xh, wm * 32, kt * 16, g, c, PS);
            ldA(al0, xl, wm * 32, kt * 16, g, c, PS);
            ldA(ah1, xh, wm * 32 + 16, kt * 16, g, c, PS);
            ldA(al1, xl, wm * 32 + 16, kt * 16, g, c, PS);
#pragma unroll
            for (int nt = 0; nt < 4; nt++) {
                uint32_t bh[2], bl[2];
                ldB(bh, wh, wn * 32 + nt * 8, kt * 16, g, c, PS);
                ldB(bl, wl, wn * 32 + nt * 8, kt * 16, g, c, PS);
                mma16816(acc[0][nt], ah0, bh);
                mma16816(acc[0][nt], ah0, bl);
                mma16816(acc[0][nt], al0, bh);
                mma16816(acc[1][nt], ah1, bh);
                mma16816(acc[1][nt], ah1, bl);
                mma16816(acc[1][nt], al1, bh);
            }
        }
        __syncthreads();
    }
#pragma unroll
    for (int mt = 0; mt < 2; mt++) {
#pragma unroll
        for (int nt = 0; nt < 4; nt++) {
            int dcol = wn * 32 + nt * 8 + 2 * c;
            float b0 = bias[dcol], b1 = bias[dcol + 1];
            size_t r0 = ((size_t)b * HWn + p0 + wm * 32 + mt * 16 + g) * 64 + dcol;
            size_t r1 = r0 + (size_t)8 * 64;
            __half h0, l0, h1, l1;
            split2(acc[mt][nt][0] + b0, h0, l0);
            split2(acc[mt][nt][1] + b1, h1, l1);
            *(uint32_t*)&Yh[r0] = pack2(h0, h1);
            *(uint32_t*)&Yl[r0] = pack2(l0, l1);
            split2(acc[mt][nt][2] + b0, h0, l0);
            split2(acc[mt][nt][3] + b1, h1, l1);
            *(uint32_t*)&Yh[r1] = pack2(h0, h1);
            *(uint32_t*)&Yl[r1] = pack2(l0, l1);
        }
    }
}

// ---------------------------------------------------------------------------
// v projection (2-term: x split, Wv plain): D[128 p, 256 o] -> g_v fp16 [b][o][p]
// grid (HWn/128, 1, B), 256 threads, warps 4(m) x 2(n of 128)
// ---------------------------------------------------------------------------
#define V_SMEM ((128*2 + 256) * PS * 2)
__global__ __launch_bounds__(256) void v_proj(
    const float* __restrict__ flow, const float* __restrict__ Wv,
    const float* __restrict__ bv)
{
    extern __shared__ __half smh[];
    __half* xh = smh;
    __half* xl = xh + 128 * PS;
    __half* wv = xl + 128 * PS;

    const int tid = threadIdx.x, w = tid >> 5, lane = tid & 31;
    const int g = lane >> 2, c = lane & 3;
    const int wm = w & 3, wn = w >> 2;
    const int p0 = blockIdx.x * 128, b = blockIdx.z;
    const float* Xb = flow + (size_t)b * Cn * HWn;

    float acc[2][16][4] = {};

    for (int kc = 0; kc < 4; kc++) {
        for (int i = tid; i < 8192; i += 256) {
            int cc = i >> 7, p = i & 127;
            __half h, l;
            split2(Xb[(size_t)(kc * 64 + cc) * HWn + p0 + p], h, l);
            xh[p * PS + cc] = h;
            xl[p * PS + cc] = l;
        }
        for (int i = tid * 2; i < 16384; i += 512) {
            int o = i >> 6, cc = i & 63;
            __half h0 = __float2half_rn(Wv[o * 256 + kc * 64 + cc]);
            __half h1 = __float2half_rn(Wv[o * 256 + kc * 64 + cc + 1]);
            *(uint32_t*)&wv[o * PS + cc] = pack2(h0, h1);
        }
        __syncthreads();
#pragma unroll
        for (int kt = 0; kt < 4; kt++) {
            uint32_t ah0[4], al0[4], ah1[4], al1[4];
            ldA(ah0, xh, wm * 32, kt * 16, g, c, PS);
            ldA(al0, xl, wm * 32, kt * 16, g, c, PS);
            ldA(ah1, xh, wm * 32 + 16, kt * 16, g, c, PS);
            ldA(al1, xl, wm * 32 + 16, kt * 16, g, c, PS);
#pragma unroll
            for (int nt = 0; nt < 16; nt++) {
                uint32_t bb[2];
                ldB(bb, wv, wn * 128 + nt * 8, kt * 16, g, c, PS);
                mma16816(acc[0][nt], ah0, bb);
                mma16816(acc[0][nt], al0, bb);
                mma16816(acc[1][nt], ah1, bb);
                mma16816(acc[1][nt], al1, bb);
            }
        }
        __syncthreads();
    }
#pragma unroll
    for (int mt = 0; mt < 2; mt++) {
#pragma unroll
        for (int nt = 0; nt < 16; nt++) {
            int o = wn * 128 + nt * 8 + 2 * c;
            int p = p0 + wm * 32 + mt * 16 + g;
            float b0 = bv[o], b1 = bv[o + 1];
            g_v[(size_t)(b * 256 + o) * HWn + p]         = __float2half_rn(acc[mt][nt][0] + b0);
            g_v[(size_t)(b * 256 + o + 1) * HWn + p]     = __float2half_rn(acc[mt][nt][1] + b1);
            g_v[(size_t)(b * 256 + o) * HWn + p + 8]     = __float2half_rn(acc[mt][nt][2] + b0);
            g_v[(size_t)(b * 256 + o + 1) * HWn + p + 8] = __float2half_rn(acc[mt][nt][3] + b1);
        }
    }
}

// ---------------------------------------------------------------------------
// Fused attention per (qt, h, b): E (3-term) -> warp softmax -> AV (2-term,
// att split + plain v slab in smem). grid (2, 128, B), 256 threads.
// smem: phase1 q/k hi+lo (110.6KB) aliased with phase2 v slab (135.2KB).
// ---------------------------------------------------------------------------
#define A_SMEM (256 * PSV * 2)
__global__ __launch_bounds__(256, 1) void attn(float* __restrict__ out)
{
    extern __shared__ __half smh[];
    __half* qh = smh;
    __half* ql = qh + 128 * PS;
    __half* kh = ql + 128 * PS;
    __half* kl = kh + 256 * PS;
    __half* vs = smh;                 // phase-2 alias over q/k

    const int tid = threadIdx.x, w = tid >> 5, lane = tid & 31;
    const int g = lane >> 2, c = lane & 3;
    const int qt = blockIdx.x, h = blockIdx.y, b = blockIdx.z;
    const int w0 = qt * 128;

    // phase 1: stage q [128][64] + k [256][64] hi/lo (uint4 copies, no convert)
    {
        const uint4* qsh = (const uint4*)(g_qh + ((size_t)b * HWn + h * Wn + w0) * 64);
        const uint4* qsl = (const uint4*)(g_ql + ((size_t)b * HWn + h * Wn + w0) * 64);
        const uint4* ksh = (const uint4*)(g_kh + ((size_t)b * HWn + h * Wn) * 64);
        const uint4* ksl = (const uint4*)(g_kl + ((size_t)b * HWn + h * Wn) * 64);
        for (int i = tid; i < 1024; i += 256) {       // q: 128 rows x 8 uint4
            int r = i >> 3, s = i & 7;
            *(uint4*)(qh + r * PS + s * 8) = qsh[i];
            *(uint4*)(ql + r * PS + s * 8) = qsl[i];
        }
        for (int i = tid; i < 2048; i += 256) {       // k: 256 rows x 8 uint4
            int r = i >> 3, s = i & 7;
            *(uint4*)(kh + r * PS + s * 8) = ksh[i];
            *(uint4*)(kl + r * PS + s * 8) = ksl[i];
        }
    }
    __syncthreads();

    // E = q k^T : warp rows w*16, all 256 keys (3-term split)
    float e[32][4] = {};
#pragma unroll
    for (int kt = 0; kt < 4; kt++) {
        uint32_t ah[4], al[4];
        ldA(ah, qh, w * 16, kt * 16, g, c, PS);
        ldA(al, ql, w * 16, kt * 16, g, c, PS);
#pragma unroll
        for (int nt = 0; nt < 32; nt++) {
            uint32_t bh[2], bl[2];
            ldB(bh, kh, nt * 8, kt * 16, g, c, PS);
            ldB(bl, kl, nt * 8, kt * 16, g, c, PS);
            mma16816(e[nt], ah, bh);
            mma16816(e[nt], ah, bl);
            mma16816(e[nt], al, bh);
        }
    }
    __syncthreads();   // all warps done reading q/k smem

    // phase 2: stage v slab [256 o][256 j] plain fp16 into aliased smem
    {
        const __half* vg = g_v + (size_t)b * 256 * HWn + h * Wn;
        for (int i = tid; i < 8192; i += 256) {       // 256 rows x 32 uint4
            int o = i >> 5, s = i & 31;
            *(uint4*)(vs + o * PSV + s * 8) = *(const uint4*)(vg + (size_t)o * HWn + s * 8);
        }
    }

    // warp-local softmax (lane owns rows g, g+8; cols spread over c)
    float m0 = -1e30f, m1 = -1e30f;
#pragma unroll
    for (int nt = 0; nt < 32; nt++) {
        m0 = fmaxf(m0, fmaxf(e[nt][0], e[nt][1]));
        m1 = fmaxf(m1, fmaxf(e[nt][2], e[nt][3]));
    }
    m0 = fmaxf(m0, __shfl_xor_sync(0xffffffffu, m0, 1));
    m0 = fmaxf(m0, __shfl_xor_sync(0xffffffffu, m0, 2));
    m1 = fmaxf(m1, __shfl_xor_sync(0xffffffffu, m1, 1));
    m1 = fmaxf(m1, __shfl_xor_sync(0xffffffffu, m1, 2));

    float s0 = 0.f, s1 = 0.f;
    uint32_t ah_[64], al_[64];
#pragma unroll
    for (int nt = 0; nt < 32; nt++) {
        float p00 = __expf(e[nt][0] - m0), p01 = __expf(e[nt][1] - m0);
        float p10 = __expf(e[nt][2] - m1), p11 = __expf(e[nt][3] - m1);
        s0 += p00 + p01;
        s1 += p10 + p11;
        __half h0, l0, h1, l1;
        split2(p00, h0, l0); split2(p01, h1, l1);
        ah_[2 * nt] = pack2(h0, h1); al_[2 * nt] = pack2(l0, l1);
        split2(p10, h0, l0); split2(p11, h1, l1);
        ah_[2 * nt + 1] = pack2(h0, h1); al_[2 * nt + 1] = pack2(l0, l1);
    }
    s0 += __shfl_xor_sync(0xffffffffu, s0, 1);
    s0 += __shfl_xor_sync(0xffffffffu, s0, 2);
    s1 += __shfl_xor_sync(0xffffffffu, s1, 1);
    s1 += __shfl_xor_sync(0xffffffffu, s1, 2);
    const float rinv0 = 1.0f / s0, rinv1 = 1.0f / s1;

    __syncthreads();   // v slab staged

    // AV: D[16 q, 256 o] per warp, K = 256 keys; 2 o-chunks of 128
    for (int och = 0; och < 2; och++) {
        float oacc[16][4] = {};
#pragma unroll
        for (int kt = 0; kt < 16; kt++) {
            const uint32_t* Ah = &ah_[4 * kt];
            const uint32_t* Al = &al_[4 * kt];
#pragma unroll
            for (int nt = 0; nt < 16; nt++) {
                uint32_t bb[2];
                ldB(bb, vs, och * 128 + nt * 8, kt * 16, g, c, PSV);
                mma16816(oacc[nt], Ah, bb);
                mma16816(oacc[nt], Al, bb);
            }
        }
#pragma unroll
        for (int nt = 0; nt < 16; nt++) {
            int o = och * 128 + nt * 8 + 2 * c;
            size_t i0 = (size_t)(b * 256 + o) * HWn + h * Wn + w0 + w * 16 + g;
            out[i0]           = oacc[nt][0] * rinv0;
            out[i0 + HWn]     = oacc[nt][1] * rinv0;
            out[i0 + 8]       = oacc[nt][2] * rinv1;
            out[i0 + HWn + 8] = oacc[nt][3] * rinv1;
        }
    }
}

// ---------------------------------------------------------------------------
extern "C" void kernel_launch(void* const* d_in, const int* in_sizes, int n_in,
                              void* d_out, int out_size)
{
    const float* flow   = (const float*)d_in[0];
    const float* de_out = (const float*)d_in[1];
    const float* Wq     = (const float*)d_in[2];
    const float* bq     = (const float*)d_in[3];
    const float* Wk     = (const float*)d_in[4];
    const float* bk     = (const float*)d_in[5];
    const float* Wv     = (const float*)d_in[6];
    const float* bv     = (const float*)d_in[7];
    float* out = (float*)d_out;

    cudaFuncSetAttribute(qk_proj, cudaFuncAttributeMaxDynamicSharedMemorySize, QK_SMEM);
    cudaFuncSetAttribute(v_proj,  cudaFuncAttributeMaxDynamicSharedMemorySize, V_SMEM);
    cudaFuncSetAttribute(attn,    cudaFuncAttributeMaxDynamicSharedMemorySize, A_SMEM);

    qk_proj<<<dim3(HWn / 128, 2, Bn), 256, QK_SMEM>>>(de_out, flow, Wq, bq, Wk, bk);
    v_proj<<<dim3(HWn / 128, 1, Bn), 256, V_SMEM>>>(flow, Wv, bv);
    attn<<<dim3(Wn / 128, Hn, Bn), 256, A_SMEM>>>(out);
}

// round 8
// speedup vs baseline: 2.9650x; 1.1298x over previous
#include <cuda_runtime.h>
#include <cuda_fp16.h>
#include <cstdint>

#define Bn 4
#define Cn 256
#define Hn 128
#define Wn 256
#define HWn 32768
#define PS 72    // smem stride (halves) for 64-wide K-chunk tiles
#define PSV 264  // smem stride (halves) for v slab [256 o][256 j]

// q,k pre-split hi/lo fp16 [b][p][64]; v plain fp16 [b][o][p]
__device__ __half g_qh[(size_t)Bn * HWn * 64];
__device__ __half g_ql[(size_t)Bn * HWn * 64];
__device__ __half g_kh[(size_t)Bn * HWn * 64];
__device__ __half g_kl[(size_t)Bn * HWn * 64];
__device__ __half g_v [(size_t)Bn * 256 * HWn];

// ---------------- helpers ----------------
static __device__ __forceinline__ void split2(float x, __half& h, __half& l) {
    h = __float2half_rn(x);
    l = __float2half_rn(x - __half2float(h));
}
static __device__ __forceinline__ uint32_t pack2(__half a, __half b) {
    __half2 t = __halves2half2(a, b);
    return *(uint32_t*)&t;
}
static __device__ __forceinline__ uint32_t sptr(const void* p) {
    return (uint32_t)__cvta_generic_to_shared(p);
}
static __device__ __forceinline__ void mma16816(float* d, const uint32_t* a, const uint32_t* b) {
    asm volatile("mma.sync.aligned.m16n8k16.row.col.f32.f16.f16.f32 "
        "{%0,%1,%2,%3}, {%4,%5,%6,%7}, {%8,%9}, {%0,%1,%2,%3};"
        : "+f"(d[0]), "+f"(d[1]), "+f"(d[2]), "+f"(d[3])
        : "r"(a[0]), "r"(a[1]), "r"(a[2]), "r"(a[3]), "r"(b[0]), "r"(b[1]));
}
// A m16xk16 fragment via one ldmatrix.x4 (row-major smem [m][k])
static __device__ __forceinline__ void ldmA(uint32_t* a, const __half* t, int m0, int k0,
                                            int lane, int stride) {
    const __half* p = t + (m0 + (lane & 15)) * stride + k0 + ((lane >> 4) << 3);
    asm volatile("ldmatrix.sync.aligned.m8n8.x4.shared.b16 {%0,%1,%2,%3}, [%4];"
        : "=r"(a[0]), "=r"(a[1]), "=r"(a[2]), "=r"(a[3]) : "r"(sptr(p)));
}
// TWO adjacent B k16xn8 fragments (n0 and n0+8) via one ldmatrix.x4
// (row-major smem [n][k]); b[0..1] -> tile n0, b[2..3] -> tile n0+8
static __device__ __forceinline__ void ldmB2(uint32_t* b, const __half* t, int n0, int k0,
                                             int lane, int stride) {
    int grp = lane >> 3;
    const __half* p = t + (n0 + ((grp & 2) << 2) + (lane & 7)) * stride + k0 + ((grp & 1) << 3);
    asm volatile("ldmatrix.sync.aligned.m8n8.x4.shared.b16 {%0,%1,%2,%3}, [%4];"
        : "=r"(b[0]), "=r"(b[1]), "=r"(b[2]), "=r"(b[3]) : "r"(sptr(p)));
}
#define CP16(d, s)  asm volatile("cp.async.cg.shared.global [%0], [%1], 16;" :: "r"(d), "l"(s))
#define CPCOMMIT()  asm volatile("cp.async.commit_group;")
#define CPWAIT0()   asm volatile("cp.async.wait_group 0;" ::: "memory")

// ---------------------------------------------------------------------------
// q/k projection (3-term split): D[128 p, 64 d] = X^T * W^T + bias
// grid (HWn/128, 2, B), 256 threads, warps 4(m) x 2(n). Out: hi/lo half pairs.
// ---------------------------------------------------------------------------
#define QK_SMEM ((128*2 + 64*2) * PS * 2)
__global__ __launch_bounds__(256) void qk_proj(
    const float* __restrict__ de_out, const float* __restrict__ flow,
    const float* __restrict__ Wq, const float* __restrict__ bq,
    const float* __restrict__ Wk, const float* __restrict__ bk)
{
    extern __shared__ __half smh[];
    __half* xh = smh;
    __half* xl = xh + 128 * PS;
    __half* wh = xl + 128 * PS;
    __half* wl = wh + 64 * PS;

    const int tid = threadIdx.x, w = tid >> 5, lane = tid & 31;
    const int c = lane & 3;
    const int wm = w & 3, wn = w >> 2;
    const int g = lane >> 2;
    const int p0 = blockIdx.x * 128, isK = blockIdx.y, b = blockIdx.z;

    const float* X    = isK ? flow : de_out;
    const float* Wm   = isK ? Wk : Wq;
    const float* bias = isK ? bk : bq;
    __half*      Yh   = isK ? g_kh : g_qh;
    __half*      Yl   = isK ? g_kl : g_ql;
    const float* Xb = X + (size_t)b * Cn * HWn;

    float acc[2][4][4] = {};

    for (int kc = 0; kc < 4; kc++) {
        // X chunk [128 p][64 c], float4 over p
        for (int i = tid; i < 2048; i += 256) {
            int cc = i >> 5, p = (i & 31) * 4;
            float4 xv = *(const float4*)&Xb[(size_t)(kc * 64 + cc) * HWn + p0 + p];
            __half h, l;
            split2(xv.x, h, l); xh[p * PS + cc] = h; xl[p * PS + cc] = l;
            split2(xv.y, h, l); xh[(p + 1) * PS + cc] = h; xl[(p + 1) * PS + cc] = l;
            split2(xv.z, h, l); xh[(p + 2) * PS + cc] = h; xl[(p + 2) * PS + cc] = l;
            split2(xv.w, h, l); xh[(p + 3) * PS + cc] = h; xl[(p + 3) * PS + cc] = l;
        }
        // W chunk [64 d][64 c], float4 over c
        for (int i = tid; i < 1024; i += 256) {
            int d = i >> 4, cc = (i & 15) * 4;
            float4 wv4 = *(const float4*)&Wm[d * 256 + kc * 64 + cc];
            __half h0, l0, h1, l1;
            split2(wv4.x, h0, l0); split2(wv4.y, h1, l1);
            *(uint32_t*)&wh[d * PS + cc] = pack2(h0, h1);
            *(uint32_t*)&wl[d * PS + cc] = pack2(l0, l1);
            split2(wv4.z, h0, l0); split2(wv4.w, h1, l1);
            *(uint32_t*)&wh[d * PS + cc + 2] = pack2(h0, h1);
            *(uint32_t*)&wl[d * PS + cc + 2] = pack2(l0, l1);
        }
        __syncthreads();
#pragma unroll
        for (int kt = 0; kt < 4; kt++) {
            uint32_t ah0[4], al0[4], ah1[4], al1[4];
            ldmA(ah0, xh, wm * 32, kt * 16, lane, PS);
            ldmA(al0, xl, wm * 32, kt * 16, lane, PS);
            ldmA(ah1, xh, wm * 32 + 16, kt * 16, lane, PS);
            ldmA(al1, xl, wm * 32 + 16, kt * 16, lane, PS);
#pragma unroll
            for (int nt = 0; nt < 4; nt += 2) {
                uint32_t bh[4], bl[4];
                ldmB2(bh, wh, wn * 32 + nt * 8, kt * 16, lane, PS);
                ldmB2(bl, wl, wn * 32 + nt * 8, kt * 16, lane, PS);
                mma16816(acc[0][nt], ah0, bh);
                mma16816(acc[0][nt], ah0, bl);
                mma16816(acc[0][nt], al0, bh);
                mma16816(acc[1][nt], ah1, bh);
                mma16816(acc[1][nt], ah1, bl);
                mma16816(acc[1][nt], al1, bh);
                mma16816(acc[0][nt + 1], ah0, bh + 2);
                mma16816(acc[0][nt + 1], ah0, bl + 2);
                mma16816(acc[0][nt + 1], al0, bh + 2);
                mma16816(acc[1][nt + 1], ah1, bh + 2);
                mma16816(acc[1][nt + 1], ah1, bl + 2);
                mma16816(acc[1][nt + 1], al1, bh + 2);
            }
        }
        __syncthreads();
    }
#pragma unroll
    for (int mt = 0; mt < 2; mt++) {
#pragma unroll
        for (int nt = 0; nt < 4; nt++) {
            int dcol = wn * 32 + nt * 8 + 2 * c;
            float b0 = bias[dcol], b1 = bias[dcol + 1];
            size_t r0 = ((size_t)b * HWn + p0 + wm * 32 + mt * 16 + g) * 64 + dcol;
            size_t r1 = r0 + (size_t)8 * 64;
            __half h0, l0, h1, l1;
            split2(acc[mt][nt][0] + b0, h0, l0);
            split2(acc[mt][nt][1] + b1, h1, l1);
            *(uint32_t*)&Yh[r0] = pack2(h0, h1);
            *(uint32_t*)&Yl[r0] = pack2(l0, l1);
            split2(acc[mt][nt][2] + b0, h0, l0);
            split2(acc[mt][nt][3] + b1, h1, l1);
            *(uint32_t*)&Yh[r1] = pack2(h0, h1);
            *(uint32_t*)&Yl[r1] = pack2(l0, l1);
        }
    }
}

// ---------------------------------------------------------------------------
// v projection (1-term, plain fp16): D[128 p, 256 o] -> g_v fp16 [b][o][p]
// grid (HWn/128, 1, B), 256 threads, warps 4(m) x 2(n of 128)
// ---------------------------------------------------------------------------
#define V_SMEM ((128 + 256) * PS * 2)
__global__ __launch_bounds__(256) void v_proj(
    const float* __restrict__ flow, const float* __restrict__ Wv,
    const float* __restrict__ bv)
{
    extern __shared__ __half smh[];
    __half* xs = smh;
    __half* wv = xs + 128 * PS;

    const int tid = threadIdx.x, w = tid >> 5, lane = tid & 31;
    const int c = lane & 3, g = lane >> 2;
    const int wm = w & 3, wn = w >> 2;
    const int p0 = blockIdx.x * 128, b = blockIdx.z;
    const float* Xb = flow + (size_t)b * Cn * HWn;

    float acc[2][16][4] = {};

    for (int kc = 0; kc < 4; kc++) {
        for (int i = tid; i < 2048; i += 256) {
            int cc = i >> 5, p = (i & 31) * 4;
            float4 xv = *(const float4*)&Xb[(size_t)(kc * 64 + cc) * HWn + p0 + p];
            xs[p * PS + cc]       = __float2half_rn(xv.x);
            xs[(p + 1) * PS + cc] = __float2half_rn(xv.y);
            xs[(p + 2) * PS + cc] = __float2half_rn(xv.z);
            xs[(p + 3) * PS + cc] = __float2half_rn(xv.w);
        }
        for (int i = tid; i < 4096; i += 256) {
            int o = i >> 4, cc = (i & 15) * 4;
            float4 wv4 = *(const float4*)&Wv[o * 256 + kc * 64 + cc];
            *(uint32_t*)&wv[o * PS + cc]     = pack2(__float2half_rn(wv4.x), __float2half_rn(wv4.y));
            *(uint32_t*)&wv[o * PS + cc + 2] = pack2(__float2half_rn(wv4.z), __float2half_rn(wv4.w));
        }
        __syncthreads();
#pragma unroll
        for (int kt = 0; kt < 4; kt++) {
            uint32_t a0[4], a1[4];
            ldmA(a0, xs, wm * 32, kt * 16, lane, PS);
            ldmA(a1, xs, wm * 32 + 16, kt * 16, lane, PS);
#pragma unroll
            for (int nt = 0; nt < 16; nt += 2) {
                uint32_t bb[4];
                ldmB2(bb, wv, wn * 128 + nt * 8, kt * 16, lane, PS);
                mma16816(acc[0][nt], a0, bb);
                mma16816(acc[1][nt], a1, bb);
                mma16816(acc[0][nt + 1], a0, bb + 2);
                mma16816(acc[1][nt + 1], a1, bb + 2);
            }
        }
        __syncthreads();
    }
#pragma unroll
    for (int mt = 0; mt < 2; mt++) {
#pragma unroll
        for (int nt = 0; nt < 16; nt++) {
            int o = wn * 128 + nt * 8 + 2 * c;
            int p = p0 + wm * 32 + mt * 16 + g;
            float b0 = bv[o], b1 = bv[o + 1];
            g_v[(size_t)(b * 256 + o) * HWn + p]         = __float2half_rn(acc[mt][nt][0] + b0);
            g_v[(size_t)(b * 256 + o + 1) * HWn + p]     = __float2half_rn(acc[mt][nt][1] + b1);
            g_v[(size_t)(b * 256 + o) * HWn + p + 8]     = __float2half_rn(acc[mt][nt][2] + b0);
            g_v[(size_t)(b * 256 + o + 1) * HWn + p + 8] = __float2half_rn(acc[mt][nt][3] + b1);
        }
    }
}

// ---------------------------------------------------------------------------
// Fused attention per (qt, h, b): E (3-term) -> warp softmax -> AV (1-term).
// grid (2, 128, B), 256 threads. smem phase1 q/k hi+lo aliased with v slab.
// ---------------------------------------------------------------------------
#define A_SMEM (256 * PSV * 2)
__global__ __launch_bounds__(256, 1) void attn(float* __restrict__ out)
{
    extern __shared__ __half smh[];
    __half* qh = smh;
    __half* ql = qh + 128 * PS;
    __half* kh = ql + 128 * PS;
    __half* kl = kh + 256 * PS;
    __half* vs = smh;                 // phase-2 alias over q/k

    const int tid = threadIdx.x, w = tid >> 5, lane = tid & 31;
    const int c = lane & 3, g = lane >> 2;
    const int qt = blockIdx.x, h = blockIdx.y, b = blockIdx.z;
    const int w0 = qt * 128;

    // phase 1: stage q/k hi+lo via cp.async
    {
        const __half* qsh = g_qh + ((size_t)b * HWn + h * Wn + w0) * 64;
        const __half* qsl = g_ql + ((size_t)b * HWn + h * Wn + w0) * 64;
        const __half* ksh = g_kh + ((size_t)b * HWn + h * Wn) * 64;
        const __half* ksl = g_kl + ((size_t)b * HWn + h * Wn) * 64;
        for (int i = tid; i < 1024; i += 256) {
            int r = i >> 3, s = (i & 7) * 8;
            CP16(sptr(qh + r * PS + s), qsh + r * 64 + s);
            CP16(sptr(ql + r * PS + s), qsl + r * 64 + s);
        }
        for (int i = tid; i < 2048; i += 256) {
            int r = i >> 3, s = (i & 7) * 8;
            CP16(sptr(kh + r * PS + s), ksh + r * 64 + s);
            CP16(sptr(kl + r * PS + s), ksl + r * 64 + s);
        }
        CPCOMMIT();
        CPWAIT0();
    }
    __syncthreads();

    // E = q k^T : warp rows w*16, all 256 keys (3-term split)
    float e[32][4] = {};
#pragma unroll
    for (int kt = 0; kt < 4; kt++) {
        uint32_t ah[4], al[4];
        ldmA(ah, qh, w * 16, kt * 16, lane, PS);
        ldmA(al, ql, w * 16, kt * 16, lane, PS);
#pragma unroll
        for (int nt = 0; nt < 32; nt += 2) {
            uint32_t bh[4], bl[4];
            ldmB2(bh, kh, nt * 8, kt * 16, lane, PS);
            ldmB2(bl, kl, nt * 8, kt * 16, lane, PS);
            mma16816(e[nt], ah, bh);
            mma16816(e[nt], ah, bl);
            mma16816(e[nt], al, bh);
            mma16816(e[nt + 1], ah, bh + 2);
            mma16816(e[nt + 1], ah, bl + 2);
            mma16816(e[nt + 1], al, bh + 2);
        }
    }
    __syncthreads();   // all warps done reading q/k smem

    // phase 2: cp.async v slab [256 o][256 j] into aliased smem (overlaps softmax)
    {
        const __half* vg = g_v + (size_t)b * 256 * HWn + h * Wn;
        for (int i = tid; i < 8192; i += 256) {
            int o = i >> 5, s = (i & 31) * 8;
            CP16(sptr(vs + o * PSV + s), vg + (size_t)o * HWn + s);
        }
        CPCOMMIT();
    }

    // warp-local softmax (lane owns rows g, g+8; cols spread over c)
    float m0 = -1e30f, m1 = -1e30f;
#pragma unroll
    for (int nt = 0; nt < 32; nt++) {
        m0 = fmaxf(m0, fmaxf(e[nt][0], e[nt][1]));
        m1 = fmaxf(m1, fmaxf(e[nt][2], e[nt][3]));
    }
    m0 = fmaxf(m0, __shfl_xor_sync(0xffffffffu, m0, 1));
    m0 = fmaxf(m0, __shfl_xor_sync(0xffffffffu, m0, 2));
    m1 = fmaxf(m1, __shfl_xor_sync(0xffffffffu, m1, 1));
    m1 = fmaxf(m1, __shfl_xor_sync(0xffffffffu, m1, 2));

    float s0 = 0.f, s1 = 0.f;
    uint32_t ah_[64];
#pragma unroll
    for (int nt = 0; nt < 32; nt++) {
        float p00 = __expf(e[nt][0] - m0), p01 = __expf(e[nt][1] - m0);
        float p10 = __expf(e[nt][2] - m1), p11 = __expf(e[nt][3] - m1);
        s0 += p00 + p01;
        s1 += p10 + p11;
        ah_[2 * nt]     = pack2(__float2half_rn(p00), __float2half_rn(p01));
        ah_[2 * nt + 1] = pack2(__float2half_rn(p10), __float2half_rn(p11));
    }
    s0 += __shfl_xor_sync(0xffffffffu, s0, 1);
    s0 += __shfl_xor_sync(0xffffffffu, s0, 2);
    s1 += __shfl_xor_sync(0xffffffffu, s1, 1);
    s1 += __shfl_xor_sync(0xffffffffu, s1, 2);
    const float rinv0 = 1.0f / s0, rinv1 = 1.0f / s1;

    CPWAIT0();
    __syncthreads();   // v slab staged

    // AV: D[16 q, 256 o] per warp, K = 256 keys; 2 o-chunks of 128 (1-term)
    for (int och = 0; och < 2; och++) {
        float oacc[16][4] = {};
#pragma unroll
        for (int kt = 0; kt < 16; kt++) {
            const uint32_t* Ah = &ah_[4 * kt];
#pragma unroll
            for (int nt = 0; nt < 16; nt += 2) {
                uint32_t bb[4];
                ldmB2(bb, vs, och * 128 + nt * 8, kt * 16, lane, PSV);
                mma16816(oacc[nt], Ah, bb);
                mma16816(oacc[nt + 1], Ah, bb + 2);
            }
        }
#pragma unroll
        for (int nt = 0; nt < 16; nt++) {
            int o = och * 128 + nt * 8 + 2 * c;
            size_t i0 = (size_t)(b * 256 + o) * HWn + h * Wn + w0 + w * 16 + g;
            out[i0]           = oacc[nt][0] * rinv0;
            out[i0 + HWn]     = oacc[nt][1] * rinv0;
            out[i0 + 8]       = oacc[nt][2] * rinv1;
            out[i0 + HWn + 8] = oacc[nt][3] * rinv1;
        }
    }
}

// ---------------------------------------------------------------------------
extern "C" void kernel_launch(void* const* d_in, const int* in_sizes, int n_in,
                              void* d_out, int out_size)
{
    const float* flow   = (const float*)d_in[0];
    const float* de_out = (const float*)d_in[1];
    const float* Wq     = (const float*)d_in[2];
    const float* bq     = (const float*)d_in[3];
    const float* Wk     = (const float*)d_in[4];
    const float* bk     = (const float*)d_in[5];
    const float* Wv     = (const float*)d_in[6];
    const float* bv     = (const float*)d_in[7];
    float* out = (float*)d_out;

    cudaFuncSetAttribute(qk_proj, cudaFuncAttributeMaxDynamicSharedMemorySize, QK_SMEM);
    cudaFuncSetAttribute(v_proj,  cudaFuncAttributeMaxDynamicSharedMemorySize, V_SMEM);
    cudaFuncSetAttribute(attn,    cudaFuncAttributeMaxDynamicSharedMemorySize, A_SMEM);

    qk_proj<<<dim3(HWn / 128, 2, Bn), 256, QK_SMEM>>>(de_out, flow, Wq, bq, Wk, bk);
    v_proj<<<dim3(HWn / 128, 1, Bn), 256, V_SMEM>>>(flow, Wv, bv);
    attn<<<dim3(Wn / 128, Hn, Bn), 256, A_SMEM>>>(out);
}

// round 9
// speedup vs baseline: 4.3477x; 1.4664x over previous
#include <cuda_runtime.h>
#include <cuda_fp16.h>
#include <cstdint>

#define Bn 4
#define Cn 256
#define Hn 128
#define Wn 256
#define HWn 32768
#define PS 72    // smem stride (halves) for 64-wide K-chunk tiles
#define PSV 264  // smem stride (halves) for v chunk [128 o][256 j]

// q,k pre-split hi/lo fp16 [b][p][64]; v plain fp16 [b][o][p]
__device__ __half g_qh[(size_t)Bn * HWn * 64];
__device__ __half g_ql[(size_t)Bn * HWn * 64];
__device__ __half g_kh[(size_t)Bn * HWn * 64];
__device__ __half g_kl[(size_t)Bn * HWn * 64];
__device__ __half g_v [(size_t)Bn * 256 * HWn];

// ---------------- helpers ----------------
static __device__ __forceinline__ void split2(float x, __half& h, __half& l) {
    h = __float2half_rn(x);
    l = __float2half_rn(x - __half2float(h));
}
static __device__ __forceinline__ uint32_t pack2(__half a, __half b) {
    __half2 t = __halves2half2(a, b);
    return *(uint32_t*)&t;
}
static __device__ __forceinline__ uint32_t sptr(const void* p) {
    return (uint32_t)__cvta_generic_to_shared(p);
}
static __device__ __forceinline__ void mma16816(float* d, const uint32_t* a, const uint32_t* b) {
    asm volatile("mma.sync.aligned.m16n8k16.row.col.f32.f16.f16.f32 "
        "{%0,%1,%2,%3}, {%4,%5,%6,%7}, {%8,%9}, {%0,%1,%2,%3};"
        : "+f"(d[0]), "+f"(d[1]), "+f"(d[2]), "+f"(d[3])
        : "r"(a[0]), "r"(a[1]), "r"(a[2]), "r"(a[3]), "r"(b[0]), "r"(b[1]));
}
// A m16xk16 fragment via one ldmatrix.x4 (row-major smem [m][k])
static __device__ __forceinline__ void ldmA(uint32_t* a, const __half* t, int m0, int k0,
                                            int lane, int stride) {
    const __half* p = t + (m0 + (lane & 15)) * stride + k0 + ((lane >> 4) << 3);
    asm volatile("ldmatrix.sync.aligned.m8n8.x4.shared.b16 {%0,%1,%2,%3}, [%4];"
        : "=r"(a[0]), "=r"(a[1]), "=r"(a[2]), "=r"(a[3]) : "r"(sptr(p)));
}
// TWO adjacent B k16xn8 fragments (n0 and n0+8) via one ldmatrix.x4
// (row-major smem [n][k]); b[0..1] -> tile n0, b[2..3] -> tile n0+8
static __device__ __forceinline__ void ldmB2(uint32_t* b, const __half* t, int n0, int k0,
                                             int lane, int stride) {
    int grp = lane >> 3;
    const __half* p = t + (n0 + ((grp & 2) << 2) + (lane & 7)) * stride + k0 + ((grp & 1) << 3);
    asm volatile("ldmatrix.sync.aligned.m8n8.x4.shared.b16 {%0,%1,%2,%3}, [%4];"
        : "=r"(b[0]), "=r"(b[1]), "=r"(b[2]), "=r"(b[3]) : "r"(sptr(p)));
}
#define CP16(d, s)  asm volatile("cp.async.cg.shared.global [%0], [%1], 16;" :: "r"(d), "l"(s))
#define CPCOMMIT()  asm volatile("cp.async.commit_group;")
#define CPWAIT(n)   asm volatile("cp.async.wait_group %0;" :: "n"(n) : "memory")

// ---------------------------------------------------------------------------
// q/k projection (3-term split): D[128 p, 64 d] = X^T * W^T + bias
// grid (HWn/128, 2, B), 256 threads, warps 4(m) x 2(n). Out: hi/lo half pairs.
// ---------------------------------------------------------------------------
#define QK_SMEM ((128*2 + 64*2) * PS * 2)
__global__ __launch_bounds__(256) void qk_proj(
    const float* __restrict__ de_out, const float* __restrict__ flow,
    const float* __restrict__ Wq, const float* __restrict__ bq,
    const float* __restrict__ Wk, const float* __restrict__ bk)
{
    extern __shared__ __half smh[];
    __half* xh = smh;
    __half* xl = xh + 128 * PS;
    __half* wh = xl + 128 * PS;
    __half* wl = wh + 64 * PS;

    const int tid = threadIdx.x, w = tid >> 5, lane = tid & 31;
    const int c = lane & 3;
    const int wm = w & 3, wn = w >> 2;
    const int g = lane >> 2;
    const int p0 = blockIdx.x * 128, isK = blockIdx.y, b = blockIdx.z;

    const float* X    = isK ? flow : de_out;
    const float* Wm   = isK ? Wk : Wq;
    const float* bias = isK ? bk : bq;
    __half*      Yh   = isK ? g_kh : g_qh;
    __half*      Yl   = isK ? g_kl : g_ql;
    const float* Xb = X + (size_t)b * Cn * HWn;

    float acc[2][4][4] = {};

    for (int kc = 0; kc < 4; kc++) {
        // X chunk [128 p][64 c]: thread handles 4 channel rows at one pixel
        // -> 4 coalesced LDGs, one 8B STS per array (4-way max conflict)
        for (int i = tid; i < 2048; i += 256) {
            int p = i & 127, cg = i >> 7;   // cg 0..15
            const float* src = &Xb[(size_t)(kc * 64 + cg * 4) * HWn + p0 + p];
            __half h0, l0, h1, l1;
            uint2 hv, lv;
            split2(src[0], h0, l0);
            split2(src[(size_t)HWn], h1, l1);
            hv.x = pack2(h0, h1); lv.x = pack2(l0, l1);
            split2(src[2 * (size_t)HWn], h0, l0);
            split2(src[3 * (size_t)HWn], h1, l1);
            hv.y = pack2(h0, h1); lv.y = pack2(l0, l1);
            *(uint2*)&xh[p * PS + cg * 4] = hv;
            *(uint2*)&xl[p * PS + cg * 4] = lv;
        }
        // W chunk [64 d][64 c], row-wise (conflict-free)
        for (int i = tid; i < 1024; i += 256) {
            int d = i >> 4, cc = (i & 15) * 4;
            float4 wv4 = *(const float4*)&Wm[d * 256 + kc * 64 + cc];
            __half h0, l0, h1, l1;
            split2(wv4.x, h0, l0); split2(wv4.y, h1, l1);
            *(uint32_t*)&wh[d * PS + cc] = pack2(h0, h1);
            *(uint32_t*)&wl[d * PS + cc] = pack2(l0, l1);
            split2(wv4.z, h0, l0); split2(wv4.w, h1, l1);
            *(uint32_t*)&wh[d * PS + cc + 2] = pack2(h0, h1);
            *(uint32_t*)&wl[d * PS + cc + 2] = pack2(l0, l1);
        }
        __syncthreads();
#pragma unroll
        for (int kt = 0; kt < 4; kt++) {
            uint32_t ah0[4], al0[4], ah1[4], al1[4];
            ldmA(ah0, xh, wm * 32, kt * 16, lane, PS);
            ldmA(al0, xl, wm * 32, kt * 16, lane, PS);
            ldmA(ah1, xh, wm * 32 + 16, kt * 16, lane, PS);
            ldmA(al1, xl, wm * 32 + 16, kt * 16, lane, PS);
#pragma unroll
            for (int nt = 0; nt < 4; nt += 2) {
                uint32_t bh[4], bl[4];
                ldmB2(bh, wh, wn * 32 + nt * 8, kt * 16, lane, PS);
                ldmB2(bl, wl, wn * 32 + nt * 8, kt * 16, lane, PS);
                mma16816(acc[0][nt], ah0, bh);
                mma16816(acc[0][nt], ah0, bl);
                mma16816(acc[0][nt], al0, bh);
                mma16816(acc[1][nt], ah1, bh);
                mma16816(acc[1][nt], ah1, bl);
                mma16816(acc[1][nt], al1, bh);
                mma16816(acc[0][nt + 1], ah0, bh + 2);
                mma16816(acc[0][nt + 1], ah0, bl + 2);
                mma16816(acc[0][nt + 1], al0, bh + 2);
                mma16816(acc[1][nt + 1], ah1, bh + 2);
                mma16816(acc[1][nt + 1], ah1, bl + 2);
                mma16816(acc[1][nt + 1], al1, bh + 2);
            }
        }
        __syncthreads();
    }
#pragma unroll
    for (int mt = 0; mt < 2; mt++) {
#pragma unroll
        for (int nt = 0; nt < 4; nt++) {
            int dcol = wn * 32 + nt * 8 + 2 * c;
            float b0 = bias[dcol], b1 = bias[dcol + 1];
            size_t r0 = ((size_t)b * HWn + p0 + wm * 32 + mt * 16 + g) * 64 + dcol;
            size_t r1 = r0 + (size_t)8 * 64;
            __half h0, l0, h1, l1;
            split2(acc[mt][nt][0] + b0, h0, l0);
            split2(acc[mt][nt][1] + b1, h1, l1);
            *(uint32_t*)&Yh[r0] = pack2(h0, h1);
            *(uint32_t*)&Yl[r0] = pack2(l0, l1);
            split2(acc[mt][nt][2] + b0, h0, l0);
            split2(acc[mt][nt][3] + b1, h1, l1);
            *(uint32_t*)&Yh[r1] = pack2(h0, h1);
            *(uint32_t*)&Yl[r1] = pack2(l0, l1);
        }
    }
}

// ---------------------------------------------------------------------------
// v projection (1-term, plain fp16): D[128 p, 256 o] -> g_v fp16 [b][o][p]
// grid (HWn/128, 1, B), 256 threads, warps 4(m) x 2(n of 128)
// ---------------------------------------------------------------------------
#define V_SMEM ((128 + 256) * PS * 2)
__global__ __launch_bounds__(256) void v_proj(
    const float* __restrict__ flow, const float* __restrict__ Wv,
    const float* __restrict__ bv)
{
    extern __shared__ __half smh[];
    __half* xs = smh;
    __half* wv = xs + 128 * PS;

    const int tid = threadIdx.x, w = tid >> 5, lane = tid & 31;
    const int c = lane & 3, g = lane >> 2;
    const int wm = w & 3, wn = w >> 2;
    const int p0 = blockIdx.x * 128, b = blockIdx.z;
    const float* Xb = flow + (size_t)b * Cn * HWn;

    float acc[2][16][4] = {};

    for (int kc = 0; kc < 4; kc++) {
        // X chunk [128 p][64 c]: 4 channel rows per thread, one 8B STS
        for (int i = tid; i < 2048; i += 256) {
            int p = i & 127, cg = i >> 7;
            const float* src = &Xb[(size_t)(kc * 64 + cg * 4) * HWn + p0 + p];
            uint2 hv;
            hv.x = pack2(__float2half_rn(src[0]), __float2half_rn(src[(size_t)HWn]));
            hv.y = pack2(__float2half_rn(src[2 * (size_t)HWn]), __float2half_rn(src[3 * (size_t)HWn]));
            *(uint2*)&xs[p * PS + cg * 4] = hv;
        }
        for (int i = tid; i < 4096; i += 256) {
            int o = i >> 4, cc = (i & 15) * 4;
            float4 wv4 = *(const float4*)&Wv[o * 256 + kc * 64 + cc];
            *(uint32_t*)&wv[o * PS + cc]     = pack2(__float2half_rn(wv4.x), __float2half_rn(wv4.y));
            *(uint32_t*)&wv[o * PS + cc + 2] = pack2(__float2half_rn(wv4.z), __float2half_rn(wv4.w));
        }
        __syncthreads();
#pragma unroll
        for (int kt = 0; kt < 4; kt++) {
            uint32_t a0[4], a1[4];
            ldmA(a0, xs, wm * 32, kt * 16, lane, PS);
            ldmA(a1, xs, wm * 32 + 16, kt * 16, lane, PS);
#pragma unroll
            for (int nt = 0; nt < 16; nt += 2) {
                uint32_t bb[4];
                ldmB2(bb, wv, wn * 128 + nt * 8, kt * 16, lane, PS);
                mma16816(acc[0][nt], a0, bb);
                mma16816(acc[1][nt], a1, bb);
                mma16816(acc[0][nt + 1], a0, bb + 2);
                mma16816(acc[1][nt + 1], a1, bb + 2);
            }
        }
        __syncthreads();
    }
#pragma unroll
    for (int mt = 0; mt < 2; mt++) {
#pragma unroll
        for (int nt = 0; nt < 16; nt++) {
            int o = wn * 128 + nt * 8 + 2 * c;
            int p = p0 + wm * 32 + mt * 16 + g;
            float b0 = bv[o], b1 = bv[o + 1];
            g_v[(size_t)(b * 256 + o) * HWn + p]         = __float2half_rn(acc[mt][nt][0] + b0);
            g_v[(size_t)(b * 256 + o + 1) * HWn + p]     = __float2half_rn(acc[mt][nt][1] + b1);
            g_v[(size_t)(b * 256 + o) * HWn + p + 8]     = __float2half_rn(acc[mt][nt][2] + b0);
            g_v[(size_t)(b * 256 + o + 1) * HWn + p + 8] = __float2half_rn(acc[mt][nt][3] + b1);
        }
    }
}

// ---------------------------------------------------------------------------
// Fused attention per (qt, h, b): E (3-term) -> warp softmax -> AV (1-term).
// grid (2, 128, B), 256 threads.
// smem: region A = q/k hi+lo (110592 B, later aliased by v chunk1),
//       region B = v chunk0 (67584 B). v chunk0 prefetch overlaps E phase;
//       v chunk1 load overlaps softmax + AV chunk0.
// ---------------------------------------------------------------------------
#define A_SMEM (110592 + 67584)
__global__ __launch_bounds__(256, 1) void attn(float* __restrict__ out)
{
    extern __shared__ __half smh[];
    __half* qh = smh;
    __half* ql = qh + 128 * PS;
    __half* kh = ql + 128 * PS;
    __half* kl = kh + 256 * PS;         // region A ends at 55296 halves
    __half* vs0 = smh + 55296;          // region B: v rows 0..127
    __half* vs1 = smh;                  // alias region A: v rows 128..255

    const int tid = threadIdx.x, w = tid >> 5, lane = tid & 31;
    const int c = lane & 3, g = lane >> 2;
    const int qt = blockIdx.x, h = blockIdx.y, b = blockIdx.z;
    const int w0 = qt * 128;
    const __half* vg = g_v + (size_t)b * 256 * HWn + h * Wn;

    // group 0: q/k hi+lo
    {
        const __half* qsh = g_qh + ((size_t)b * HWn + h * Wn + w0) * 64;
        const __half* qsl = g_ql + ((size_t)b * HWn + h * Wn + w0) * 64;
        const __half* ksh = g_kh + ((size_t)b * HWn + h * Wn) * 64;
        const __half* ksl = g_kl + ((size_t)b * HWn + h * Wn) * 64;
        for (int i = tid; i < 1024; i += 256) {
            int r = i >> 3, s = (i & 7) * 8;
            CP16(sptr(qh + r * PS + s), qsh + r * 64 + s);
            CP16(sptr(ql + r * PS + s), qsl + r * 64 + s);
        }
        for (int i = tid; i < 2048; i += 256) {
            int r = i >> 3, s = (i & 7) * 8;
            CP16(sptr(kh + r * PS + s), ksh + r * 64 + s);
            CP16(sptr(kl + r * PS + s), ksl + r * 64 + s);
        }
        CPCOMMIT();
    }
    // group 1: v chunk0 (overlaps E phase)
    for (int i = tid; i < 4096; i += 256) {
        int o = i >> 5, s = (i & 31) * 8;
        CP16(sptr(vs0 + o * PSV + s), vg + (size_t)o * HWn + s);
    }
    CPCOMMIT();

    CPWAIT(1);          // q/k ready (v chunk0 may still be in flight)
    __syncthreads();

    // E = q k^T : warp rows w*16, all 256 keys (3-term split)
    float e[32][4] = {};
#pragma unroll
    for (int kt = 0; kt < 4; kt++) {
        uint32_t ah[4], al[4];
        ldmA(ah, qh, w * 16, kt * 16, lane, PS);
        ldmA(al, ql, w * 16, kt * 16, lane, PS);
#pragma unroll
        for (int nt = 0; nt < 32; nt += 2) {
            uint32_t bh[4], bl[4];
            ldmB2(bh, kh, nt * 8, kt * 16, lane, PS);
            ldmB2(bl, kl, nt * 8, kt * 16, lane, PS);
            mma16816(e[nt], ah, bh);
            mma16816(e[nt], ah, bl);
            mma16816(e[nt], al, bh);
            mma16816(e[nt + 1], ah, bh + 2);
            mma16816(e[nt + 1], ah, bl + 2);
            mma16816(e[nt + 1], al, bh + 2);
        }
    }
    __syncthreads();    // all warps done reading q/k smem

    // group 2: v chunk1 into aliased region A (overlaps softmax + AV chunk0)
    for (int i = tid; i < 4096; i += 256) {
        int o = i >> 5, s = (i & 31) * 8;
        CP16(sptr(vs1 + o * PSV + s), vg + (size_t)(o + 128) * HWn + s);
    }
    CPCOMMIT();

    // warp-local softmax (lane owns rows g, g+8; cols spread over c)
    float m0 = -1e30f, m1 = -1e30f;
#pragma unroll
    for (int nt = 0; nt < 32; nt++) {
        m0 = fmaxf(m0, fmaxf(e[nt][0], e[nt][1]));
        m1 = fmaxf(m1, fmaxf(e[nt][2], e[nt][3]));
    }
    m0 = fmaxf(m0, __shfl_xor_sync(0xffffffffu, m0, 1));
    m0 = fmaxf(m0, __shfl_xor_sync(0xffffffffu, m0, 2));
    m1 = fmaxf(m1, __shfl_xor_sync(0xffffffffu, m1, 1));
    m1 = fmaxf(m1, __shfl_xor_sync(0xffffffffu, m1, 2));

    float s0 = 0.f, s1 = 0.f;
    uint32_t ah_[64];
#pragma unroll
    for (int nt = 0; nt < 32; nt++) {
        float p00 = __expf(e[nt][0] - m0), p01 = __expf(e[nt][1] - m0);
        float p10 = __expf(e[nt][2] - m1), p11 = __expf(e[nt][3] - m1);
        s0 += p00 + p01;
        s1 += p10 + p11;
        ah_[2 * nt]     = pack2(__float2half_rn(p00), __float2half_rn(p01));
        ah_[2 * nt + 1] = pack2(__float2half_rn(p10), __float2half_rn(p11));
    }
    s0 += __shfl_xor_sync(0xffffffffu, s0, 1);
    s0 += __shfl_xor_sync(0xffffffffu, s0, 2);
    s1 += __shfl_xor_sync(0xffffffffu, s1, 1);
    s1 += __shfl_xor_sync(0xffffffffu, s1, 2);
    const float rinv0 = 1.0f / s0, rinv1 = 1.0f / s1;

    // AV chunk 0 (o 0..127) from vs0
    CPWAIT(1);          // v chunk0 done (chunk1 may still be in flight)
    __syncthreads();
    {
        float oacc[16][4] = {};
#pragma unroll
        for (int kt = 0; kt < 16; kt++) {
            const uint32_t* Ah = &ah_[4 * kt];
#pragma unroll
            for (int nt = 0; nt < 16; nt += 2) {
                uint32_t bb[4];
                ldmB2(bb, vs0, nt * 8, kt * 16, lane, PSV);
                mma16816(oacc[nt], Ah, bb);
                mma16816(oacc[nt + 1], Ah, bb + 2);
            }
        }
#pragma unroll
        for (int nt = 0; nt < 16; nt++) {
            int o = nt * 8 + 2 * c;
            size_t i0 = (size_t)(b * 256 + o) * HWn + h * Wn + w0 + w * 16 + g;
            out[i0]           = oacc[nt][0] * rinv0;
            out[i0 + HWn]     = oacc[nt][1] * rinv0;
            out[i0 + 8]       = oacc[nt][2] * rinv1;
            out[i0 + HWn + 8] = oacc[nt][3] * rinv1;
        }
    }

    // AV chunk 1 (o 128..255) from vs1
    CPWAIT(0);
    __syncthreads();
    {
        float oacc[16][4] = {};
#pragma unroll
        for (int kt = 0; kt < 16; kt++) {
            const uint32_t* Ah = &ah_[4 * kt];
#pragma unroll
            for (int nt = 0; nt < 16; nt += 2) {
                uint32_t bb[4];
                ldmB2(bb, vs1, nt * 8, kt * 16, lane, PSV);
                mma16816(oacc[nt], Ah, bb);
                mma16816(oacc[nt + 1], Ah, bb + 2);
            }
        }
#pragma unroll
        for (int nt = 0; nt < 16; nt++) {
            int o = 128 + nt * 8 + 2 * c;
            size_t i0 = (size_t)(b * 256 + o) * HWn + h * Wn + w0 + w * 16 + g;
            out[i0]           = oacc[nt][0] * rinv0;
            out[i0 + HWn]     = oacc[nt][1] * rinv0;
            out[i0 + 8]       = oacc[nt][2] * rinv1;
            out[i0 + HWn + 8] = oacc[nt][3] * rinv1;
        }
    }
}

// ---------------------------------------------------------------------------
extern "C" void kernel_launch(void* const* d_in, const int* in_sizes, int n_in,
                              void* d_out, int out_size)
{
    const float* flow   = (const float*)d_in[0];
    const float* de_out = (const float*)d_in[1];
    const float* Wq     = (const float*)d_in[2];
    const float* bq     = (const float*)d_in[3];
    const float* Wk     = (const float*)d_in[4];
    const float* bk     = (const float*)d_in[5];
    const float* Wv     = (const float*)d_in[6];
    const float* bv     = (const float*)d_in[7];
    float* out = (float*)d_out;

    cudaFuncSetAttribute(qk_proj, cudaFuncAttributeMaxDynamicSharedMemorySize, QK_SMEM);
    cudaFuncSetAttribute(v_proj,  cudaFuncAttributeMaxDynamicSharedMemorySize, V_SMEM);
    cudaFuncSetAttribute(attn,    cudaFuncAttributeMaxDynamicSharedMemorySize, A_SMEM);

    qk_proj<<<dim3(HWn / 128, 2, Bn), 256, QK_SMEM>>>(de_out, flow, Wq, bq, Wk, bk);
    v_proj<<<dim3(HWn / 128, 1, Bn), 256, V_SMEM>>>(flow, Wv, bv);
    attn<<<dim3(Wn / 128, Hn, Bn), 256, A_SMEM>>>(out);
}

// round 10
// speedup vs baseline: 5.5906x; 1.2859x over previous
#include <cuda_runtime.h>
#include <cuda_fp16.h>
#include <cstdint>

#define Bn 4
#define Cn 256
#define Hn 128
#define Wn 256
#define HWn 32768
#define PS 72    // smem stride (halves) for 64-wide K-chunk tiles
#define PSV 264  // smem stride (halves) for 256-wide rows

// q,k pre-split hi/lo fp16 [b][p][64]; v plain fp16 [b][o][p]
__device__ __half g_qh[(size_t)Bn * HWn * 64];
__device__ __half g_ql[(size_t)Bn * HWn * 64];
__device__ __half g_kh[(size_t)Bn * HWn * 64];
__device__ __half g_kl[(size_t)Bn * HWn * 64];
__device__ __half g_v [(size_t)Bn * 256 * HWn];
// pre-converted weights
__device__ __half g_wqh[64 * 256], g_wql[64 * 256];
__device__ __half g_wkh[64 * 256], g_wkl[64 * 256];
__device__ __half g_wv16[256 * 256];

// ---------------- helpers ----------------
static __device__ __forceinline__ void split2(float x, __half& h, __half& l) {
    h = __float2half_rn(x);
    l = __float2half_rn(x - __half2float(h));
}
static __device__ __forceinline__ uint32_t pack2(__half a, __half b) {
    __half2 t = __halves2half2(a, b);
    return *(uint32_t*)&t;
}
static __device__ __forceinline__ uint32_t sptr(const void* p) {
    return (uint32_t)__cvta_generic_to_shared(p);
}
static __device__ __forceinline__ void mma16816(float* d, const uint32_t* a, const uint32_t* b) {
    asm volatile("mma.sync.aligned.m16n8k16.row.col.f32.f16.f16.f32 "
        "{%0,%1,%2,%3}, {%4,%5,%6,%7}, {%8,%9}, {%0,%1,%2,%3};"
        : "+f"(d[0]), "+f"(d[1]), "+f"(d[2]), "+f"(d[3])
        : "r"(a[0]), "r"(a[1]), "r"(a[2]), "r"(a[3]), "r"(b[0]), "r"(b[1]));
}
static __device__ __forceinline__ void ldmA(uint32_t* a, const __half* t, int m0, int k0,
                                            int lane, int stride) {
    const __half* p = t + (m0 + (lane & 15)) * stride + k0 + ((lane >> 4) << 3);
    asm volatile("ldmatrix.sync.aligned.m8n8.x4.shared.b16 {%0,%1,%2,%3}, [%4];"
        : "=r"(a[0]), "=r"(a[1]), "=r"(a[2]), "=r"(a[3]) : "r"(sptr(p)));
}
static __device__ __forceinline__ void ldmB2(uint32_t* b, const __half* t, int n0, int k0,
                                             int lane, int stride) {
    int grp = lane >> 3;
    const __half* p = t + (n0 + ((grp & 2) << 2) + (lane & 7)) * stride + k0 + ((grp & 1) << 3);
    asm volatile("ldmatrix.sync.aligned.m8n8.x4.shared.b16 {%0,%1,%2,%3}, [%4];"
        : "=r"(b[0]), "=r"(b[1]), "=r"(b[2]), "=r"(b[3]) : "r"(sptr(p)));
}
#define CP16(d, s)  asm volatile("cp.async.cg.shared.global [%0], [%1], 16;" :: "r"(d), "l"(s))
#define CPCOMMIT()  asm volatile("cp.async.commit_group;")
#define CPWAIT(n)   asm volatile("cp.async.wait_group %0;" :: "n"(n) : "memory")

// ---------------------------------------------------------------------------
// prep: Wq/Wk -> hi/lo fp16, Wv -> fp16. grid 192 x 256, 2 elems/thread.
// ---------------------------------------------------------------------------
__global__ void prep(const float* __restrict__ Wq, const float* __restrict__ Wk,
                     const float* __restrict__ Wv)
{
    int i = (blockIdx.x * 256 + threadIdx.x) * 2;
    __half h0, l0, h1, l1;
    if (i < 16384) {
        split2(Wq[i], h0, l0); split2(Wq[i + 1], h1, l1);
        *(uint32_t*)&g_wqh[i] = pack2(h0, h1);
        *(uint32_t*)&g_wql[i] = pack2(l0, l1);
    } else if (i < 32768) {
        int j = i - 16384;
        split2(Wk[j], h0, l0); split2(Wk[j + 1], h1, l1);
        *(uint32_t*)&g_wkh[j] = pack2(h0, h1);
        *(uint32_t*)&g_wkl[j] = pack2(l0, l1);
    } else {
        int j = i - 32768;
        *(uint32_t*)&g_wv16[j] = pack2(__float2half_rn(Wv[j]), __float2half_rn(Wv[j + 1]));
    }
}

// ---------------------------------------------------------------------------
// q/k projection (3-term split): D[128 p, 64 d] = X^T * W^T + bias
// grid (HWn/128, 2, B), 256 threads. W via double-buffered cp.async (fp16).
// smem: xh/xl 2x9216h + 2 W bufs of (wh 4608h + wl 4608h) = 36864 h = 73728 B
// ---------------------------------------------------------------------------
#define QK_SMEM 73728
__global__ __launch_bounds__(256) void qk_proj(
    const float* __restrict__ de_out, const float* __restrict__ flow,
    const float* __restrict__ bq, const float* __restrict__ bk)
{
    extern __shared__ __half smh[];
    __half* xh = smh;
    __half* xl = smh + 9216;

    const int tid = threadIdx.x, w = tid >> 5, lane = tid & 31;
    const int c = lane & 3, g = lane >> 2;
    const int wm = w & 3, wn = w >> 2;
    const int p0 = blockIdx.x * 128, isK = blockIdx.y, b = blockIdx.z;

    const float*  X    = isK ? flow : de_out;
    const float*  bias = isK ? bk : bq;
    const __half* wsh  = isK ? g_wkh : g_wqh;
    const __half* wsl  = isK ? g_wkl : g_wql;
    __half*       Yh   = isK ? g_kh : g_qh;
    __half*       Yl   = isK ? g_kl : g_ql;
    const float* Xb = X + (size_t)b * Cn * HWn;

    float acc[2][4][4] = {};

    // issue W chunk 0
    {
        __half* wb = smh + 18432;
        for (int i = tid; i < 512; i += 256) {
            int d = i >> 3, s = (i & 7) * 8;
            CP16(sptr(wb + d * PS + s), wsh + d * 256 + s);
            CP16(sptr(wb + 4608 + d * PS + s), wsl + d * 256 + s);
        }
        CPCOMMIT();
    }

    for (int kc = 0; kc < 4; kc++) {
        if (kc < 3) {   // issue W chunk kc+1 into other buf (overlaps X staging + MMA)
            __half* wb = smh + 18432 + ((kc + 1) & 1) * 9216;
            for (int i = tid; i < 512; i += 256) {
                int d = i >> 3, s = (i & 7) * 8;
                CP16(sptr(wb + d * PS + s), wsh + d * 256 + (kc + 1) * 64 + s);
                CP16(sptr(wb + 4608 + d * PS + s), wsl + d * 256 + (kc + 1) * 64 + s);
            }
            CPCOMMIT();
        }
        // X chunk [128 p][64 c]: 4 channel rows per thread, one 8B STS per array
        for (int i = tid; i < 2048; i += 256) {
            int p = i & 127, cg = i >> 7;
            const float* src = &Xb[(size_t)(kc * 64 + cg * 4) * HWn + p0 + p];
            __half h0, l0, h1, l1;
            uint2 hv, lv;
            split2(src[0], h0, l0);
            split2(src[(size_t)HWn], h1, l1);
            hv.x = pack2(h0, h1); lv.x = pack2(l0, l1);
            split2(src[2 * (size_t)HWn], h0, l0);
            split2(src[3 * (size_t)HWn], h1, l1);
            hv.y = pack2(h0, h1); lv.y = pack2(l0, l1);
            *(uint2*)&xh[p * PS + cg * 4] = hv;
            *(uint2*)&xl[p * PS + cg * 4] = lv;
        }
        if (kc < 3) CPWAIT(1); else CPWAIT(0);
        __syncthreads();

        const __half* wh = smh + 18432 + (kc & 1) * 9216;
        const __half* wl = wh + 4608;
#pragma unroll
        for (int kt = 0; kt < 4; kt++) {
            uint32_t ah0[4], al0[4], ah1[4], al1[4];
            ldmA(ah0, xh, wm * 32, kt * 16, lane, PS);
            ldmA(al0, xl, wm * 32, kt * 16, lane, PS);
            ldmA(ah1, xh, wm * 32 + 16, kt * 16, lane, PS);
            ldmA(al1, xl, wm * 32 + 16, kt * 16, lane, PS);
#pragma unroll
            for (int nt = 0; nt < 4; nt += 2) {
                uint32_t bh[4], bl[4];
                ldmB2(bh, wh, wn * 32 + nt * 8, kt * 16, lane, PS);
                ldmB2(bl, wl, wn * 32 + nt * 8, kt * 16, lane, PS);
                mma16816(acc[0][nt], ah0, bh);
                mma16816(acc[0][nt], ah0, bl);
                mma16816(acc[0][nt], al0, bh);
                mma16816(acc[1][nt], ah1, bh);
                mma16816(acc[1][nt], ah1, bl);
                mma16816(acc[1][nt], al1, bh);
                mma16816(acc[0][nt + 1], ah0, bh + 2);
                mma16816(acc[0][nt + 1], ah0, bl + 2);
                mma16816(acc[0][nt + 1], al0, bh + 2);
                mma16816(acc[1][nt + 1], ah1, bh + 2);
                mma16816(acc[1][nt + 1], ah1, bl + 2);
                mma16816(acc[1][nt + 1], al1, bh + 2);
            }
        }
        __syncthreads();
    }
#pragma unroll
    for (int mt = 0; mt < 2; mt++) {
#pragma unroll
        for (int nt = 0; nt < 4; nt++) {
            int dcol = wn * 32 + nt * 8 + 2 * c;
            float b0 = bias[dcol], b1 = bias[dcol + 1];
            size_t r0 = ((size_t)b * HWn + p0 + wm * 32 + mt * 16 + g) * 64 + dcol;
            size_t r1 = r0 + (size_t)8 * 64;
            __half h0, l0, h1, l1;
            split2(acc[mt][nt][0] + b0, h0, l0);
            split2(acc[mt][nt][1] + b1, h1, l1);
            *(uint32_t*)&Yh[r0] = pack2(h0, h1);
            *(uint32_t*)&Yl[r0] = pack2(l0, l1);
            split2(acc[mt][nt][2] + b0, h0, l0);
            split2(acc[mt][nt][3] + b1, h1, l1);
            *(uint32_t*)&Yh[r1] = pack2(h0, h1);
            *(uint32_t*)&Yl[r1] = pack2(l0, l1);
        }
    }
}

// ---------------------------------------------------------------------------
// v projection (1-term): D[128 p, 256 o] -> g_v fp16 [b][o][p]
// grid (HWn/128, 1, B), 256 threads, 2 blocks/SM.
// X staged once [128p][256c] (67584 B); Wv tiles [128o][64c] fp16 cp.async
// double-buffered (2 x 18432 B). Two sequential o-halves, 64-float accum.
// ---------------------------------------------------------------------------
#define V_SMEM (67584 + 2 * 18432)
static __device__ __forceinline__ void issue_wv_tile(__half* smh, int tid, int t) {
    __half* wb = smh + 33792 + (t & 1) * 9216;
    int oh = t >> 2, kc = t & 3;
    for (int i = tid; i < 1024; i += 256) {
        int o = i >> 3, s = (i & 7) * 8;
        CP16(sptr(wb + o * PS + s), g_wv16 + (size_t)(oh * 128 + o) * 256 + kc * 64 + s);
    }
    CPCOMMIT();
}
__global__ __launch_bounds__(256, 2) void v_proj(
    const float* __restrict__ flow, const float* __restrict__ bv)
{
    extern __shared__ __half smh[];
    __half* xs = smh;   // [128][264]

    const int tid = threadIdx.x, w = tid >> 5, lane = tid & 31;
    const int c = lane & 3, g = lane >> 2;
    const int wm = w & 3, wn = w >> 2;
    const int p0 = blockIdx.x * 128, b = blockIdx.z;
    const float* Xb = flow + (size_t)b * Cn * HWn;

    issue_wv_tile(smh, tid, 0);
    issue_wv_tile(smh, tid, 1);

    // stage full X [128p][256c] fp16 (overlaps W DMA)
    for (int i = tid; i < 8192; i += 256) {
        int p = i & 127, cg = i >> 7;
        const float* src = &Xb[(size_t)(cg * 4) * HWn + p0 + p];
        uint2 hv;
        hv.x = pack2(__float2half_rn(src[0]), __float2half_rn(src[(size_t)HWn]));
        hv.y = pack2(__float2half_rn(src[2 * (size_t)HWn]), __float2half_rn(src[3 * (size_t)HWn]));
        *(uint2*)&xs[p * PSV + cg * 4] = hv;
    }
    __syncthreads();

    for (int oh = 0; oh < 2; oh++) {
        float acc[2][8][4] = {};
        for (int kc = 0; kc < 4; kc++) {
            int t = oh * 4 + kc;
            if (t < 7) CPWAIT(1); else CPWAIT(0);
            __syncthreads();
            const __half* wb = smh + 33792 + (t & 1) * 9216;
#pragma unroll
            for (int ktc = 0; ktc < 4; ktc++) {
                uint32_t a0[4], a1[4];
                ldmA(a0, xs, wm * 32, kc * 64 + ktc * 16, lane, PSV);
                ldmA(a1, xs, wm * 32 + 16, kc * 64 + ktc * 16, lane, PSV);
#pragma unroll
                for (int ntp = 0; ntp < 4; ntp++) {
                    uint32_t bb[4];
                    ldmB2(bb, wb, wn * 64 + ntp * 16, ktc * 16, lane, PS);
                    mma16816(acc[0][2 * ntp], a0, bb);
                    mma16816(acc[1][2 * ntp], a1, bb);
                    mma16816(acc[0][2 * ntp + 1], a0, bb + 2);
                    mma16816(acc[1][2 * ntp + 1], a1, bb + 2);
                }
            }
            __syncthreads();
            if (t + 2 <= 7) issue_wv_tile(smh, tid, t + 2);
        }
#pragma unroll
        for (int mt = 0; mt < 2; mt++) {
#pragma unroll
            for (int nt = 0; nt < 8; nt++) {
                int o = oh * 128 + wn * 64 + nt * 8 + 2 * c;
                int p = p0 + wm * 32 + mt * 16 + g;
                float b0 = bv[o], b1 = bv[o + 1];
                g_v[(size_t)(b * 256 + o) * HWn + p]         = __float2half_rn(acc[mt][nt][0] + b0);
                g_v[(size_t)(b * 256 + o + 1) * HWn + p]     = __float2half_rn(acc[mt][nt][1] + b1);
                g_v[(size_t)(b * 256 + o) * HWn + p + 8]     = __float2half_rn(acc[mt][nt][2] + b0);
                g_v[(size_t)(b * 256 + o + 1) * HWn + p + 8] = __float2half_rn(acc[mt][nt][3] + b1);
            }
        }
    }
}

// ---------------------------------------------------------------------------
// Fused attention per (qt, h, b): E (3-term) -> warp softmax -> AV (1-term).
// Unchanged from R9 (known-good).
// ---------------------------------------------------------------------------
#define A_SMEM (110592 + 67584)
__global__ __launch_bounds__(256, 1) void attn(float* __restrict__ out)
{
    extern __shared__ __half smh[];
    __half* qh = smh;
    __half* ql = qh + 128 * PS;
    __half* kh = ql + 128 * PS;
    __half* kl = kh + 256 * PS;
    __half* vs0 = smh + 55296;
    __half* vs1 = smh;

    const int tid = threadIdx.x, w = tid >> 5, lane = tid & 31;
    const int c = lane & 3, g = lane >> 2;
    const int qt = blockIdx.x, h = blockIdx.y, b = blockIdx.z;
    const int w0 = qt * 128;
    const __half* vg = g_v + (size_t)b * 256 * HWn + h * Wn;

    {
        const __half* qsh = g_qh + ((size_t)b * HWn + h * Wn + w0) * 64;
        const __half* qsl = g_ql + ((size_t)b * HWn + h * Wn + w0) * 64;
        const __half* ksh = g_kh + ((size_t)b * HWn + h * Wn) * 64;
        const __half* ksl = g_kl + ((size_t)b * HWn + h * Wn) * 64;
        for (int i = tid; i < 1024; i += 256) {
            int r = i >> 3, s = (i & 7) * 8;
            CP16(sptr(qh + r * PS + s), qsh + r * 64 + s);
            CP16(sptr(ql + r * PS + s), qsl + r * 64 + s);
        }
        for (int i = tid; i < 2048; i += 256) {
            int r = i >> 3, s = (i & 7) * 8;
            CP16(sptr(kh + r * PS + s), ksh + r * 64 + s);
            CP16(sptr(kl + r * PS + s), ksl + r * 64 + s);
        }
        CPCOMMIT();
    }
    for (int i = tid; i < 4096; i += 256) {
        int o = i >> 5, s = (i & 31) * 8;
        CP16(sptr(vs0 + o * PSV + s), vg + (size_t)o * HWn + s);
    }
    CPCOMMIT();

    CPWAIT(1);
    __syncthreads();

    float e[32][4] = {};
#pragma unroll
    for (int kt = 0; kt < 4; kt++) {
        uint32_t ah[4], al[4];
        ldmA(ah, qh, w * 16, kt * 16, lane, PS);
        ldmA(al, ql, w * 16, kt * 16, lane, PS);
#pragma unroll
        for (int nt = 0; nt < 32; nt += 2) {
            uint32_t bh[4], bl[4];
            ldmB2(bh, kh, nt * 8, kt * 16, lane, PS);
            ldmB2(bl, kl, nt * 8, kt * 16, lane, PS);
            mma16816(e[nt], ah, bh);
            mma16816(e[nt], ah, bl);
            mma16816(e[nt], al, bh);
            mma16816(e[nt + 1], ah, bh + 2);
            mma16816(e[nt + 1], ah, bl + 2);
            mma16816(e[nt + 1], al, bh + 2);
        }
    }
    __syncthreads();

    for (int i = tid; i < 4096; i += 256) {
        int o = i >> 5, s = (i & 31) * 8;
        CP16(sptr(vs1 + o * PSV + s), vg + (size_t)(o + 128) * HWn + s);
    }
    CPCOMMIT();

    float m0 = -1e30f, m1 = -1e30f;
#pragma unroll
    for (int nt = 0; nt < 32; nt++) {
        m0 = fmaxf(m0, fmaxf(e[nt][0], e[nt][1]));
        m1 = fmaxf(m1, fmaxf(e[nt][2], e[nt][3]));
    }
    m0 = fmaxf(m0, __shfl_xor_sync(0xffffffffu, m0, 1));
    m0 = fmaxf(m0, __shfl_xor_sync(0xffffffffu, m0, 2));
    m1 = fmaxf(m1, __shfl_xor_sync(0xffffffffu, m1, 1));
    m1 = fmaxf(m1, __shfl_xor_sync(0xffffffffu, m1, 2));

    float s0 = 0.f, s1 = 0.f;
    uint32_t ah_[64];
#pragma unroll
    for (int nt = 0; nt < 32; nt++) {
        float p00 = __expf(e[nt][0] - m0), p01 = __expf(e[nt][1] - m0);
        float p10 = __expf(e[nt][2] - m1), p11 = __expf(e[nt][3] - m1);
        s0 += p00 + p01;
        s1 += p10 + p11;
        ah_[2 * nt]     = pack2(__float2half_rn(p00), __float2half_rn(p01));
        ah_[2 * nt + 1] = pack2(__float2half_rn(p10), __float2half_rn(p11));
    }
    s0 += __shfl_xor_sync(0xffffffffu, s0, 1);
    s0 += __shfl_xor_sync(0xffffffffu, s0, 2);
    s1 += __shfl_xor_sync(0xffffffffu, s1, 1);
    s1 += __shfl_xor_sync(0xffffffffu, s1, 2);
    const float rinv0 = 1.0f / s0, rinv1 = 1.0f / s1;

    CPWAIT(1);
    __syncthreads();
    {
        float oacc[16][4] = {};
#pragma unroll
        for (int kt = 0; kt < 16; kt++) {
            const uint32_t* Ah = &ah_[4 * kt];
#pragma unroll
            for (int nt = 0; nt < 16; nt += 2) {
                uint32_t bb[4];
                ldmB2(bb, vs0, nt * 8, kt * 16, lane, PSV);
                mma16816(oacc[nt], Ah, bb);
                mma16816(oacc[nt + 1], Ah, bb + 2);
            }
        }
#pragma unroll
        for (int nt = 0; nt < 16; nt++) {
            int o = nt * 8 + 2 * c;
            size_t i0 = (size_t)(b * 256 + o) * HWn + h * Wn + w0 + w * 16 + g;
            out[i0]           = oacc[nt][0] * rinv0;
            out[i0 + HWn]     = oacc[nt][1] * rinv0;
            out[i0 + 8]       = oacc[nt][2] * rinv1;
            out[i0 + HWn + 8] = oacc[nt][3] * rinv1;
        }
    }

    CPWAIT(0);
    __syncthreads();
    {
        float oacc[16][4] = {};
#pragma unroll
        for (int kt = 0; kt < 16; kt++) {
            const uint32_t* Ah = &ah_[4 * kt];
#pragma unroll
            for (int nt = 0; nt < 16; nt += 2) {
                uint32_t bb[4];
                ldmB2(bb, vs1, nt * 8, kt * 16, lane, PSV);
                mma16816(oacc[nt], Ah, bb);
                mma16816(oacc[nt + 1], Ah, bb + 2);
            }
        }
#pragma unroll
        for (int nt = 0; nt < 16; nt++) {
            int o = 128 + nt * 8 + 2 * c;
            size_t i0 = (size_t)(b * 256 + o) * HWn + h * Wn + w0 + w * 16 + g;
            out[i0]           = oacc[nt][0] * rinv0;
            out[i0 + HWn]     = oacc[nt][1] * rinv0;
            out[i0 + 8]       = oacc[nt][2] * rinv1;
            out[i0 + HWn + 8] = oacc[nt][3] * rinv1;
        }
    }
}

// ---------------------------------------------------------------------------
extern "C" void kernel_launch(void* const* d_in, const int* in_sizes, int n_in,
                              void* d_out, int out_size)
{
    const float* flow   = (const float*)d_in[0];
    const float* de_out = (const float*)d_in[1];
    const float* Wq     = (const float*)d_in[2];
    const float* bq     = (const float*)d_in[3];
    const float* Wk     = (const float*)d_in[4];
    const float* bk     = (const float*)d_in[5];
    const float* Wv     = (const float*)d_in[6];
    const float* bv     = (const float*)d_in[7];
    float* out = (float*)d_out;

    cudaFuncSetAttribute(qk_proj, cudaFuncAttributeMaxDynamicSharedMemorySize, QK_SMEM);
    cudaFuncSetAttribute(v_proj,  cudaFuncAttributeMaxDynamicSharedMemorySize, V_SMEM);
    cudaFuncSetAttribute(attn,    cudaFuncAttributeMaxDynamicSharedMemorySize, A_SMEM);

    prep<<<192, 256>>>(Wq, Wk, Wv);
    qk_proj<<<dim3(HWn / 128, 2, Bn), 256, QK_SMEM>>>(de_out, flow, bq, bk);
    v_proj<<<dim3(HWn / 128, 1, Bn), 256, V_SMEM>>>(flow, bv);
    attn<<<dim3(Wn / 128, Hn, Bn), 256, A_SMEM>>>(out);
}